// round 4
// baseline (speedup 1.0000x reference)
#include <cuda_runtime.h>

#define NQ 1024
#define NK 2048
#define DD 64
#define TQ 8
#define TK1 128
#define TK2 128

// Scratch: projected q and k (b1 folded into qp). [row][h] layout.
__device__ float g_qp[NQ * DD];
__device__ float g_kp[NK * DD];

// ---------------------------------------------------------------------------
// Projection: qp[q][h] = b1[h] + sum_d W1[h][d]      * query[d][q]
//             kp[k][h] =         sum_d W1[h][64 + d] * key[d][k]
// Grid: 16 blocks for qp (64 rows each) + 32 blocks for kp.
// ---------------------------------------------------------------------------
__global__ __launch_bounds__(256) void proj_kernel(
    const float* __restrict__ q_in, const float* __restrict__ k_in,
    const float* __restrict__ W1, const float* __restrict__ b1)
{
    __shared__ float srcS[64 * 68];   // [c][d], padded
    __shared__ float wS[64 * 68];     // [h][d], padded

    const int t = threadIdx.x;
    const bool isQ = blockIdx.x < (NQ / 64);
    const int row0 = isQ ? blockIdx.x * 64 : (blockIdx.x - NQ / 64) * 64;
    const float* src = isQ ? q_in : k_in;
    const int stride = isQ ? NQ : NK;
    const int wOff = isQ ? 0 : DD;
    float* dst = isQ ? g_qp : g_kp;

    // src tile transposed into smem: srcS[c][d] = src[d][row0+c]
#pragma unroll
    for (int r = 0; r < 16; ++r) {
        int i = t + 256 * r;
        int d = i >> 6, c = i & 63;
        srcS[c * 68 + d] = src[d * stride + row0 + c];
    }
    // weight half: wS[h][d]
#pragma unroll
    for (int r = 0; r < 16; ++r) {
        int i = t + 256 * r;
        int h = i >> 6, d = i & 63;
        wS[h * 68 + d] = W1[h * 128 + wOff + d];
    }
    __syncthreads();

    const int h = t & 63;
    const int cbase = t >> 6;     // 0..3, c = cbase + 4j
    float acc[16];
#pragma unroll
    for (int j = 0; j < 16; ++j) acc[j] = 0.f;

    const float4* w4 = reinterpret_cast<const float4*>(&wS[h * 68]);
#pragma unroll
    for (int d4 = 0; d4 < 16; ++d4) {
        float4 w = w4[d4];
#pragma unroll
        for (int j = 0; j < 16; ++j) {
            int c = cbase + 4 * j;
            float4 s = *reinterpret_cast<const float4*>(&srcS[c * 68 + 4 * d4]);
            acc[j] += w.x * s.x + w.y * s.y + w.z * s.z + w.w * s.w;
        }
    }
    float bias = isQ ? b1[h] : 0.f;
#pragma unroll
    for (int j = 0; j < 16; ++j) {
        int c = cbase + 4 * j;
        dst[(row0 + c) * DD + h] = acc[j] + bias;   // coalesced over h
    }
}

// ---------------------------------------------------------------------------
// Fused scores + softmax + (prob @ value). One block per 8 q-rows.
// ---------------------------------------------------------------------------
struct SmemU {
    union {
        float kp[TK1 * 68];               // pass 1: kp tile, padded rows
        struct {
            float V[64 * 132];            // pass 2: value tile [d][k], padded
            float E[TQ * 132];            // pass 2: exp(scores-m), padded
        } p2;
    } u;
    float qp[TQ * 64];
    float w2[64];
    float m[TQ];
    float wred[8][2];
    float sums[TQ];
    float o[TQ * 64];
};

__global__ __launch_bounds__(256) void attn_kernel(
    const float* __restrict__ value, const float* __restrict__ W2,
    const float* __restrict__ b2, float* __restrict__ out,
    float* __restrict__ scores)
{
    __shared__ SmemU sm;
    const int t = threadIdx.x;
    const int qb = blockIdx.x * TQ;

    for (int i = t; i < TQ * 64; i += 256) sm.qp[i] = g_qp[qb * 64 + i];
    if (t < 64) sm.w2[t] = W2[t];
    const float b2v = b2[0];
    __syncthreads();

    // ================= pass 1: scores + row max =================
    const int kcol = t & 63;            // k lane within tile (plus +64 sibling)
    const int qpair = t >> 6;           // 0..3
    const int q0 = 2 * qpair;
    float m00 = -3.0e38f, m01 = -3.0e38f, m10 = -3.0e38f, m11 = -3.0e38f;

    for (int kt = 0; kt < NK; kt += TK1) {
        // load kp tile [TK1][64] -> stride-68 smem
#pragma unroll
        for (int r = 0; r < 8; ++r) {
            int i4 = t + 256 * r;                 // float4 index, < 2048
            int row = i4 >> 4, h4 = i4 & 15;
            float4 v = *reinterpret_cast<const float4*>(&g_kp[(kt + row) * DD + 4 * h4]);
            *reinterpret_cast<float4*>(&sm.u.kp[row * 68 + 4 * h4]) = v;
        }
        __syncthreads();

        float s00 = 0.f, s01 = 0.f, s10 = 0.f, s11 = 0.f;
        const float4* qpA = reinterpret_cast<const float4*>(&sm.qp[q0 * 64]);
        const float4* qpB = reinterpret_cast<const float4*>(&sm.qp[(q0 + 1) * 64]);
        const float4* kpA = reinterpret_cast<const float4*>(&sm.u.kp[kcol * 68]);
        const float4* kpB = reinterpret_cast<const float4*>(&sm.u.kp[(kcol + 64) * 68]);
        const float4* w24 = reinterpret_cast<const float4*>(sm.w2);

#pragma unroll
        for (int h4 = 0; h4 < 16; ++h4) {
            float4 a = qpA[h4], b = qpB[h4];
            float4 c0 = kpA[h4], c1 = kpB[h4];
            float4 w = w24[h4];
#define STEP(comp) { \
            float x0 = a.comp + c0.comp; float x1 = a.comp + c1.comp; \
            float x2 = b.comp + c0.comp; float x3 = b.comp + c1.comp; \
            x0 = fmaxf(x0, 0.f); x1 = fmaxf(x1, 0.f); \
            x2 = fmaxf(x2, 0.f); x3 = fmaxf(x3, 0.f); \
            s00 = fmaf(w.comp, x0, s00); s01 = fmaf(w.comp, x1, s01); \
            s10 = fmaf(w.comp, x2, s10); s11 = fmaf(w.comp, x3, s11); }
            STEP(x) STEP(y) STEP(z) STEP(w)
#undef STEP
        }
        s00 += b2v; s01 += b2v; s10 += b2v; s11 += b2v;
        m00 = fmaxf(m00, s00); m01 = fmaxf(m01, s01);
        m10 = fmaxf(m10, s10); m11 = fmaxf(m11, s11);
        scores[(qb + q0) * NK + kt + kcol]          = s00;
        scores[(qb + q0) * NK + kt + kcol + 64]     = s01;
        scores[(qb + q0 + 1) * NK + kt + kcol]      = s10;
        scores[(qb + q0 + 1) * NK + kt + kcol + 64] = s11;
        __syncthreads();
    }

    // row-max reduction: warp reduce, then combine warp pairs
    float mq0 = fmaxf(m00, m01), mq1 = fmaxf(m10, m11);
#pragma unroll
    for (int off = 16; off; off >>= 1) {
        mq0 = fmaxf(mq0, __shfl_xor_sync(0xffffffffu, mq0, off));
        mq1 = fmaxf(mq1, __shfl_xor_sync(0xffffffffu, mq1, off));
    }
    const int warp = t >> 5;
    if ((t & 31) == 0) { sm.wred[warp][0] = mq0; sm.wred[warp][1] = mq1; }
    __syncthreads();
    if (t < TQ) {
        int p = t >> 1, i = t & 1;
        sm.m[t] = fmaxf(sm.wred[2 * p][i], sm.wred[2 * p + 1][i]);
    }
    __syncthreads();

    // ================= pass 2: softmax + prob @ value =================
    const int qE = t >> 5;              // exp-stage q row (== warp id)
    const int kE = (t & 31) * 4;        // exp-stage k offset
    const float mE = sm.m[qE];
    float sumE = 0.f;

    const int dC = t & 63;              // compute-stage d
    const int qg = (t >> 6) & 1;        // q group: rows 0-3 or 4-7
    const int qC0 = 4 * qg;
    const int khalf = t >> 7;           // 0/1: which 64-k half of the tile
    float acc0 = 0.f, acc1 = 0.f, acc2 = 0.f, acc3 = 0.f;

    for (int kt = 0; kt < NK; kt += TK2) {
        // exp stage (reads scores this block just wrote; __syncthreads makes
        // block-local global writes visible)
        float4 sc = *reinterpret_cast<const float4*>(&scores[(qb + qE) * NK + kt + kE]);
        float4 e;
        e.x = __expf(sc.x - mE); e.y = __expf(sc.y - mE);
        e.z = __expf(sc.z - mE); e.w = __expf(sc.w - mE);
        sumE += (e.x + e.y) + (e.z + e.w);
        *reinterpret_cast<float4*>(&sm.u.p2.E[qE * 132 + kE]) = e;

        // value tile [64][TK2] -> stride-132 smem (conflict-free for strided read)
#pragma unroll
        for (int r = 0; r < 8; ++r) {
            int d = (t >> 5) + 8 * r;
            int kk = (t & 31) * 4;
            float4 v = *reinterpret_cast<const float4*>(&value[d * NK + kt + kk]);
            *reinterpret_cast<float4*>(&sm.u.p2.V[d * 132 + kk]) = v;
        }
        __syncthreads();

        const float4* V4 = reinterpret_cast<const float4*>(&sm.u.p2.V[dC * 132 + khalf * 64]);
        const float4* E04 = reinterpret_cast<const float4*>(&sm.u.p2.E[(qC0 + 0) * 132 + khalf * 64]);
        const float4* E14 = reinterpret_cast<const float4*>(&sm.u.p2.E[(qC0 + 1) * 132 + khalf * 64]);
        const float4* E24 = reinterpret_cast<const float4*>(&sm.u.p2.E[(qC0 + 2) * 132 + khalf * 64]);
        const float4* E34 = reinterpret_cast<const float4*>(&sm.u.p2.E[(qC0 + 3) * 132 + khalf * 64]);
#pragma unroll
        for (int kk = 0; kk < 16; ++kk) {
            float4 v = V4[kk];
            float4 e0 = E04[kk], e1 = E14[kk], e2 = E24[kk], e3 = E34[kk];
            acc0 = fmaf(e0.x, v.x, acc0); acc0 = fmaf(e0.y, v.y, acc0);
            acc0 = fmaf(e0.z, v.z, acc0); acc0 = fmaf(e0.w, v.w, acc0);
            acc1 = fmaf(e1.x, v.x, acc1); acc1 = fmaf(e1.y, v.y, acc1);
            acc1 = fmaf(e1.z, v.z, acc1); acc1 = fmaf(e1.w, v.w, acc1);
            acc2 = fmaf(e2.x, v.x, acc2); acc2 = fmaf(e2.y, v.y, acc2);
            acc2 = fmaf(e2.z, v.z, acc2); acc2 = fmaf(e2.w, v.w, acc2);
            acc3 = fmaf(e3.x, v.x, acc3); acc3 = fmaf(e3.y, v.y, acc3);
            acc3 = fmaf(e3.z, v.z, acc3); acc3 = fmaf(e3.w, v.w, acc3);
        }
        __syncthreads();
    }

    // combine the two k-halves
    if (khalf == 0) {
        sm.o[(qC0 + 0) * 64 + dC] = acc0;
        sm.o[(qC0 + 1) * 64 + dC] = acc1;
        sm.o[(qC0 + 2) * 64 + dC] = acc2;
        sm.o[(qC0 + 3) * 64 + dC] = acc3;
    }
    __syncthreads();
    if (khalf == 1) {
        sm.o[(qC0 + 0) * 64 + dC] += acc0;
        sm.o[(qC0 + 1) * 64 + dC] += acc1;
        sm.o[(qC0 + 2) * 64 + dC] += acc2;
        sm.o[(qC0 + 3) * 64 + dC] += acc3;
    }
    // exp-sum reduction (each warp handled exactly one q row)
#pragma unroll
    for (int off = 16; off; off >>= 1)
        sumE += __shfl_xor_sync(0xffffffffu, sumE, off);
    if ((t & 31) == 0) sm.sums[qE] = sumE;
    __syncthreads();

    // normalize + write out[d][q]
    for (int idx = t; idx < TQ * 64; idx += 256) {
        int q = idx >> 6, d = idx & 63;
        out[d * NQ + qb + q] = sm.o[q * 64 + d] / sm.sums[q];
    }
}

// ---------------------------------------------------------------------------
extern "C" void kernel_launch(void* const* d_in, const int* in_sizes, int n_in,
                              void* d_out, int out_size)
{
    const float* query = (const float*)d_in[0];   // [1,64,1024]
    const float* key   = (const float*)d_in[1];   // [1,64,2048]
    const float* value = (const float*)d_in[2];   // [1,64,2048]
    const float* W1    = (const float*)d_in[3];   // [64,128]
    const float* b1    = (const float*)d_in[4];   // [64]
    const float* W2    = (const float*)d_in[5];   // [1,64]
    const float* b2    = (const float*)d_in[6];   // [1]

    float* out    = (float*)d_out;                // [1,64,1024]
    float* scores = out + DD * NQ;                // [1,1024,2048]

    proj_kernel<<<NQ / 64 + NK / 64, 256>>>(query, key, W1, b1);
    attn_kernel<<<NQ / TQ, 256>>>(value, W2, b2, out, scores);
}

// round 6
// speedup vs baseline: 1.1237x; 1.1237x over previous
#include <cuda_runtime.h>

#define NQ 1024
#define NK 2048
#define DD 64

// Projected activations, stored TRANSPOSED: [h][row]
__device__ float g_qpT[DD * NQ];   // b1 folded in
__device__ float g_kpT[DD * NK];

// ---------------------------------------------------------------------------
// Projection: qpT[h][q] = b1[h] + sum_d W1[h][d]    * query[d][q]
//             kpT[h][k] =         sum_d W1[h][64+d] * key[d][k]
// Grid: 16 q-blocks + 32 k-blocks, 64 rows each.
// ---------------------------------------------------------------------------
__global__ __launch_bounds__(256) void proj_kernel(
    const float* __restrict__ q_in, const float* __restrict__ k_in,
    const float* __restrict__ W1, const float* __restrict__ b1)
{
    __shared__ float srcS[64 * 68];   // [c][d]
    __shared__ float wS[64 * 68];     // [h][d]
    __shared__ float oS[64 * 65];     // [h][c] staging for transposed write

    const int t = threadIdx.x;
    const bool isQ = blockIdx.x < (NQ / 64);
    const int row0 = isQ ? blockIdx.x * 64 : (blockIdx.x - NQ / 64) * 64;
    const float* src = isQ ? q_in : k_in;
    const int stride = isQ ? NQ : NK;
    const int wOff = isQ ? 0 : DD;
    float* dstT = isQ ? g_qpT : g_kpT;

#pragma unroll
    for (int r = 0; r < 16; ++r) {
        int i = t + 256 * r;
        int d = i >> 6, c = i & 63;
        srcS[c * 68 + d] = src[d * stride + row0 + c];
    }
#pragma unroll
    for (int r = 0; r < 16; ++r) {
        int i = t + 256 * r;
        int h = i >> 6, d = i & 63;
        wS[h * 68 + d] = W1[h * 128 + wOff + d];
    }
    __syncthreads();

    const int h = t & 63;
    const int cbase = t >> 6;
    float acc[16];
#pragma unroll
    for (int j = 0; j < 16; ++j) acc[j] = 0.f;

    const float4* w4 = reinterpret_cast<const float4*>(&wS[h * 68]);
#pragma unroll
    for (int d4 = 0; d4 < 16; ++d4) {
        float4 w = w4[d4];
#pragma unroll
        for (int j = 0; j < 16; ++j) {
            int c = cbase + 4 * j;
            float4 s = *reinterpret_cast<const float4*>(&srcS[c * 68 + 4 * d4]);
            acc[j] += w.x * s.x + w.y * s.y + w.z * s.z + w.w * s.w;
        }
    }
    float bias = isQ ? b1[h] : 0.f;
#pragma unroll
    for (int j = 0; j < 16; ++j) {
        int c = cbase + 4 * j;
        oS[h * 65 + c] = acc[j] + bias;   // lanes vary h -> stride 65, conflict-free
    }
    __syncthreads();
    // transposed, coalesced global write
#pragma unroll
    for (int r = 0; r < 16; ++r) {
        int i = t + 256 * r;
        int hh = i >> 6, c = i & 63;
        dstT[hh * stride + row0 + c] = oS[hh * 65 + c];
    }
}

// ---------------------------------------------------------------------------
// Scores: 64q x 64k tile per block, 4x4 microtile per thread, h-loop of 64.
// scores[q][k] = b2 + sum_h W2[h] * relu(qpT[h][q] + kpT[h][k])
// Grid: 16 * 32 = 512 blocks.
// ---------------------------------------------------------------------------
__global__ __launch_bounds__(256) void scores_kernel(
    const float* __restrict__ W2, const float* __restrict__ b2,
    float* __restrict__ scores)
{
    __shared__ float qpS[64 * 68];   // [h][q]
    __shared__ float kpS[64 * 68];   // [h][k]
    __shared__ float w2s[64];

    const int t = threadIdx.x;
    const int kb = (blockIdx.x & 31) * 64;
    const int qb = (blockIdx.x >> 5) * 64;

#pragma unroll
    for (int r = 0; r < 4; ++r) {
        int i = t + 256 * r;               // float4 index < 1024
        int h = i >> 4, off = (i & 15) * 4;
        *reinterpret_cast<float4*>(&qpS[h * 68 + off]) =
            *reinterpret_cast<const float4*>(&g_qpT[h * NQ + qb + off]);
        *reinterpret_cast<float4*>(&kpS[h * 68 + off]) =
            *reinterpret_cast<const float4*>(&g_kpT[h * NK + kb + off]);
    }
    if (t < 64) w2s[t] = W2[t];
    const float b2v = b2[0];
    __syncthreads();

    const int tk = t & 15, tq = t >> 4;
    const int q0 = 4 * tq, k0 = 4 * tk;
    float acc[4][4];
#pragma unroll
    for (int i = 0; i < 4; ++i)
#pragma unroll
        for (int j = 0; j < 4; ++j) acc[i][j] = 0.f;

#pragma unroll 4
    for (int h = 0; h < 64; ++h) {
        float4 kv = *reinterpret_cast<const float4*>(&kpS[h * 68 + k0]);
        float4 qv = *reinterpret_cast<const float4*>(&qpS[h * 68 + q0]);
        float w = w2s[h];
        float qa[4] = {qv.x, qv.y, qv.z, qv.w};
        float ka[4] = {kv.x, kv.y, kv.z, kv.w};
#pragma unroll
        for (int i = 0; i < 4; ++i)
#pragma unroll
            for (int j = 0; j < 4; ++j)
                acc[i][j] = fmaf(w, fmaxf(qa[i] + ka[j], 0.f), acc[i][j]);
    }
#pragma unroll
    for (int i = 0; i < 4; ++i) {
        float4 o = {acc[i][0] + b2v, acc[i][1] + b2v,
                    acc[i][2] + b2v, acc[i][3] + b2v};
        *reinterpret_cast<float4*>(&scores[(qb + q0 + i) * NK + kb + k0]) = o;
    }
}

// ---------------------------------------------------------------------------
// PV: softmax over scores rows + prob @ value. TQ=4 rows/block, grid 256.
// ---------------------------------------------------------------------------
#define TQ 4
#define TK 128

struct PVSmem {
    float V[64 * 132];          // value tile [d][k], padded
    float E[TQ * 132];          // exp(scores - m)
    float m[TQ];
    float red[8];
    float sums[TQ];
    float opart[4 * TQ * 64];   // [kq][q][d]
};

__global__ __launch_bounds__(256) void pv_kernel(
    const float* __restrict__ value, const float* __restrict__ scores,
    float* __restrict__ out)
{
    __shared__ PVSmem sm;
    const int t = threadIdx.x;
    const int qb = blockIdx.x * TQ;
    const int lane = t & 31, warp = t >> 5;

    // ---- row max over full NK (scores from L2) ----
    const int tr = t >> 6, tc = t & 63;     // 64 threads per row
    float mx = -3.0e38f;
#pragma unroll
    for (int j = 0; j < 8; ++j) {
        float4 s = *reinterpret_cast<const float4*>(
            &scores[(qb + tr) * NK + tc * 4 + 256 * j]);
        mx = fmaxf(mx, fmaxf(fmaxf(s.x, s.y), fmaxf(s.z, s.w)));
    }
#pragma unroll
    for (int off = 16; off; off >>= 1)
        mx = fmaxf(mx, __shfl_xor_sync(0xffffffffu, mx, off));
    if (lane == 0) sm.red[warp] = mx;
    __syncthreads();
    if (t < TQ) sm.m[t] = fmaxf(sm.red[2 * t], sm.red[2 * t + 1]);
    __syncthreads();

    // ---- main loop: exp + V tile + microtile GEMM ----
    const int rE = t >> 6;                  // exp row (== tr)
    const int cE = (t & 63) * 2;            // exp cols (pair)
    const float mE = sm.m[rE];
    float sumE = 0.f;

    const int dC = t & 63;                  // compute: d lane
    const int kq = t >> 6;                  // k quarter 0..3
    float a0 = 0.f, a1 = 0.f, a2 = 0.f, a3 = 0.f;

    for (int kt = 0; kt < NK; kt += TK) {
        float2 s = *reinterpret_cast<const float2*>(
            &scores[(qb + rE) * NK + kt + cE]);
        float e0 = __expf(s.x - mE), e1 = __expf(s.y - mE);
        sumE += e0 + e1;
        sm.E[rE * 132 + cE] = e0;
        sm.E[rE * 132 + cE + 1] = e1;

#pragma unroll
        for (int r = 0; r < 8; ++r) {
            int d = (t >> 5) + 8 * r;
            int kk = (t & 31) * 4;
            *reinterpret_cast<float4*>(&sm.V[d * 132 + kk]) =
                *reinterpret_cast<const float4*>(&value[d * NK + kt + kk]);
        }
        __syncthreads();

        const float4* V4 = reinterpret_cast<const float4*>(&sm.V[dC * 132 + kq * 32]);
        const float4* E0 = reinterpret_cast<const float4*>(&sm.E[0 * 132 + kq * 32]);
        const float4* E1 = reinterpret_cast<const float4*>(&sm.E[1 * 132 + kq * 32]);
        const float4* E2 = reinterpret_cast<const float4*>(&sm.E[2 * 132 + kq * 32]);
        const float4* E3 = reinterpret_cast<const float4*>(&sm.E[3 * 132 + kq * 32]);
#pragma unroll
        for (int kk = 0; kk < 8; ++kk) {
            float4 v = V4[kk];
            float4 e0 = E0[kk], e1 = E1[kk], e2 = E2[kk], e3 = E3[kk];
            a0 = fmaf(e0.x, v.x, a0); a0 = fmaf(e0.y, v.y, a0);
            a0 = fmaf(e0.z, v.z, a0); a0 = fmaf(e0.w, v.w, a0);
            a1 = fmaf(e1.x, v.x, a1); a1 = fmaf(e1.y, v.y, a1);
            a1 = fmaf(e1.z, v.z, a1); a1 = fmaf(e1.w, v.w, a1);
            a2 = fmaf(e2.x, v.x, a2); a2 = fmaf(e2.y, v.y, a2);
            a2 = fmaf(e2.z, v.z, a2); a2 = fmaf(e2.w, v.w, a2);
            a3 = fmaf(e3.x, v.x, a3); a3 = fmaf(e3.y, v.y, a3);
            a3 = fmaf(e3.z, v.z, a3); a3 = fmaf(e3.w, v.w, a3);
        }
        __syncthreads();
    }

    // partials per k-quarter
    sm.opart[(kq * TQ + 0) * 64 + dC] = a0;
    sm.opart[(kq * TQ + 1) * 64 + dC] = a1;
    sm.opart[(kq * TQ + 2) * 64 + dC] = a2;
    sm.opart[(kq * TQ + 3) * 64 + dC] = a3;

    // exp-sum reduction (64 threads per row)
#pragma unroll
    for (int off = 16; off; off >>= 1)
        sumE += __shfl_xor_sync(0xffffffffu, sumE, off);
    if (lane == 0) sm.red[warp] = sumE;
    __syncthreads();
    if (t < TQ) sm.sums[t] = sm.red[2 * t] + sm.red[2 * t + 1];
    __syncthreads();

    // combine quarters, normalize, write out[d][qb+q]
    {
        int q = t >> 6, d = t & 63;
        float o = sm.opart[(0 * TQ + q) * 64 + d]
                + sm.opart[(1 * TQ + q) * 64 + d]
                + sm.opart[(2 * TQ + q) * 64 + d]
                + sm.opart[(3 * TQ + q) * 64 + d];
        out[d * NQ + qb + q] = o / sm.sums[q];
    }
}

// ---------------------------------------------------------------------------
extern "C" void kernel_launch(void* const* d_in, const int* in_sizes, int n_in,
                              void* d_out, int out_size)
{
    const float* query = (const float*)d_in[0];   // [1,64,1024]
    const float* key   = (const float*)d_in[1];   // [1,64,2048]
    const float* value = (const float*)d_in[2];   // [1,64,2048]
    const float* W1    = (const float*)d_in[3];   // [64,128]
    const float* b1    = (const float*)d_in[4];   // [64]
    const float* W2    = (const float*)d_in[5];   // [1,64]
    const float* b2    = (const float*)d_in[6];   // [1]

    float* out    = (float*)d_out;                // [1,64,1024]
    float* scores = out + DD * NQ;                // [1,1024,2048]

    proj_kernel<<<NQ / 64 + NK / 64, 256>>>(query, key, W1, b1);
    scores_kernel<<<(NQ / 64) * (NK / 64), 256>>>(W2, b2, scores);
    pv_kernel<<<NQ / TQ, 256>>>(value, scores, out);
}

// round 9
// speedup vs baseline: 1.2063x; 1.0735x over previous
#include <cuda_runtime.h>

typedef unsigned long long ull;

#define NQ 1024
#define NK 2048
#define DD 64

// Scratch (static device globals — no allocation).
__device__ float g_qpT[DD * NQ];     // [h][q], b1 folded in
__device__ float g_kpT[DD * NK];     // [h][k]
__device__ float g_m[NQ];            // row max of scores
__device__ float g_sum[NQ];          // row sum of exp(scores - m)
__device__ float g_part[8 * NQ * DD];// pv partials [ksplit][q][d]

// ---- f32x2 helpers (FFMA2/FADD2 via PTX; sm_100+) ----
__device__ __forceinline__ ull addx2(ull a, ull b) {
    ull d; asm("add.rn.f32x2 %0,%1,%2;" : "=l"(d) : "l"(a), "l"(b)); return d;
}
__device__ __forceinline__ ull fmax2(ull a, ull b, ull c) {
    ull d; asm("fma.rn.f32x2 %0,%1,%2,%3;" : "=l"(d) : "l"(a), "l"(b), "l"(c)); return d;
}
__device__ __forceinline__ ull packf2(float lo, float hi) {
    ull d; asm("mov.b64 %0,{%1,%2};" : "=l"(d)
               : "r"(__float_as_uint(lo)), "r"(__float_as_uint(hi))); return d;
}
__device__ __forceinline__ float2 unpackf2(ull x) {
    unsigned lo, hi; asm("mov.b64 {%0,%1},%2;" : "=r"(lo), "=r"(hi) : "l"(x));
    return make_float2(__uint_as_float(lo), __uint_as_float(hi));
}

// ---------------------------------------------------------------------------
// Projection, 16-row tiles. Grid = 64 (q) + 128 (k) = 192 blocks.
// qpT[h][q] = b1[h] + sum_d W1[h][d]*query[d][q];  kpT[h][k] = sum_d W1[h][64+d]*key[d][k]
// ---------------------------------------------------------------------------
__global__ __launch_bounds__(256) void proj_kernel(
    const float* __restrict__ q_in, const float* __restrict__ k_in,
    const float* __restrict__ W1, const float* __restrict__ b1)
{
    __shared__ __align__(16) float srcS[16 * 68];  // [c][d]
    __shared__ __align__(16) float wS[64 * 68];    // [h][d]
    __shared__ float oS[64 * 17];                  // [h][c]

    const int t = threadIdx.x;
    const bool isQ = blockIdx.x < (NQ / 16);
    const int row0 = isQ ? blockIdx.x * 16 : (blockIdx.x - NQ / 16) * 16;
    const float* src = isQ ? q_in : k_in;
    const int stride = isQ ? NQ : NK;
    const int wOff = isQ ? 0 : DD;
    float* dstT = isQ ? g_qpT : g_kpT;

#pragma unroll
    for (int r = 0; r < 4; ++r) {
        int i = t + 256 * r;                 // < 1024
        int d = i >> 4, c = i & 15;
        srcS[c * 68 + d] = src[d * stride + row0 + c];
    }
#pragma unroll
    for (int r = 0; r < 16; ++r) {
        int i = t + 256 * r;                 // < 4096
        int h = i >> 6, d = i & 63;
        wS[h * 68 + d] = W1[h * 128 + wOff + d];
    }
    __syncthreads();

    const int h = t & 63;
    const int c0 = t >> 6;                   // c = c0 + 4j
    float acc[4] = {0.f, 0.f, 0.f, 0.f};
    const float4* w4 = reinterpret_cast<const float4*>(&wS[h * 68]);
#pragma unroll
    for (int d4 = 0; d4 < 16; ++d4) {
        float4 w = w4[d4];
#pragma unroll
        for (int j = 0; j < 4; ++j) {
            float4 s = *reinterpret_cast<const float4*>(&srcS[(c0 + 4 * j) * 68 + 4 * d4]);
            acc[j] += w.x * s.x + w.y * s.y + w.z * s.z + w.w * s.w;
        }
    }
    float bias = isQ ? b1[h] : 0.f;
#pragma unroll
    for (int j = 0; j < 4; ++j) oS[h * 17 + c0 + 4 * j] = acc[j] + bias;
    __syncthreads();
#pragma unroll
    for (int r = 0; r < 4; ++r) {
        int i = t + 256 * r;                 // < 1024
        int hh = i >> 4, c = i & 15;
        dstT[hh * stride + row0 + c] = oS[hh * 17 + c];
    }
}

// ---------------------------------------------------------------------------
// Scores: 64q x 64k per block, 4q x 4k per thread, packed f32x2 math.
// w*relu(x) = hw*x + hw*|x| with hw = w/2; |x| packed via and.b64 (2x LOP3).
// Grid 512.
// ---------------------------------------------------------------------------
__global__ __launch_bounds__(256) void scores_kernel(
    const float* __restrict__ W2, const float* __restrict__ b2,
    float* __restrict__ scores)
{
    __shared__ __align__(16) float qpS[64 * 64];   // [h][q]
    __shared__ __align__(16) float kpS[64 * 64];   // [h][k]
    __shared__ ull w2D[64];                        // packed {w/2, w/2}

    const int t = threadIdx.x;
    const int kb = (blockIdx.x & 31) * 64;
    const int qb = (blockIdx.x >> 5) * 64;

#pragma unroll
    for (int r = 0; r < 4; ++r) {
        int i = t + 256 * r;                 // float4 index < 1024
        int h = i >> 4, off = (i & 15) * 4;
        *reinterpret_cast<float4*>(&qpS[h * 64 + off]) =
            *reinterpret_cast<const float4*>(&g_qpT[h * NQ + qb + off]);
        *reinterpret_cast<float4*>(&kpS[h * 64 + off]) =
            *reinterpret_cast<const float4*>(&g_kpT[h * NK + kb + off]);
    }
    if (t < 64) { float hw = 0.5f * W2[t]; w2D[t] = packf2(hw, hw); }
    const float b2v = b2[0];
    __syncthreads();

    const int tk = t & 15, tq = t >> 4;
    const int q0 = 4 * tq, k0 = 4 * tk;
    const ull MASK = 0x7FFFFFFF7FFFFFFFULL;

    ull acc[2][4];
#pragma unroll
    for (int p = 0; p < 2; ++p)
#pragma unroll
        for (int j = 0; j < 4; ++j) acc[p][j] = 0ULL;

#pragma unroll 4
    for (int h = 0; h < 64; ++h) {
        float4 kv = *reinterpret_cast<const float4*>(&kpS[h * 64 + k0]);
        ull q2a = *reinterpret_cast<const ull*>(&qpS[h * 64 + q0]);       // (q0,q0+1)
        ull q2b = *reinterpret_cast<const ull*>(&qpS[h * 64 + q0 + 2]);   // (q0+2,q0+3)
        ull hw2 = w2D[h];
        ull kd[4];
        kd[0] = packf2(kv.x, kv.x); kd[1] = packf2(kv.y, kv.y);
        kd[2] = packf2(kv.z, kv.z); kd[3] = packf2(kv.w, kv.w);
#pragma unroll
        for (int j = 0; j < 4; ++j) {
            ull xa = addx2(q2a, kd[j]);
            ull xb = addx2(q2b, kd[j]);
            ull aa = xa & MASK;
            ull ab = xb & MASK;
            acc[0][j] = fmax2(hw2, xa, acc[0][j]);
            acc[0][j] = fmax2(hw2, aa, acc[0][j]);
            acc[1][j] = fmax2(hw2, xb, acc[1][j]);
            acc[1][j] = fmax2(hw2, ab, acc[1][j]);
        }
    }

#pragma unroll
    for (int p = 0; p < 2; ++p) {
        float2 u0 = unpackf2(acc[p][0]);
        float2 u1 = unpackf2(acc[p][1]);
        float2 u2 = unpackf2(acc[p][2]);
        float2 u3 = unpackf2(acc[p][3]);
        float4 lo = {u0.x + b2v, u1.x + b2v, u2.x + b2v, u3.x + b2v};
        float4 hi = {u0.y + b2v, u1.y + b2v, u2.y + b2v, u3.y + b2v};
        *reinterpret_cast<float4*>(&scores[(qb + q0 + 2 * p) * NK + kb + k0]) = lo;
        *reinterpret_cast<float4*>(&scores[(qb + q0 + 2 * p + 1) * NK + kb + k0]) = hi;
    }
}

// ---------------------------------------------------------------------------
// Row stats: max and sum(exp(s - m)) per q row. 1 warp / row, grid 128.
// ---------------------------------------------------------------------------
__global__ __launch_bounds__(256) void rowstat_kernel(const float* __restrict__ scores)
{
    const int t = threadIdx.x;
    const int lane = t & 31, warp = t >> 5;
    const int row = blockIdx.x * 8 + warp;
    const float4* S = reinterpret_cast<const float4*>(&scores[row * NK]);

    float mx = -3.0e38f;
#pragma unroll
    for (int j = 0; j < 16; ++j) {
        float4 s = S[lane + 32 * j];
        mx = fmaxf(mx, fmaxf(fmaxf(s.x, s.y), fmaxf(s.z, s.w)));
    }
#pragma unroll
    for (int off = 16; off; off >>= 1)
        mx = fmaxf(mx, __shfl_xor_sync(0xffffffffu, mx, off));

    float sum = 0.f;
#pragma unroll
    for (int j = 0; j < 16; ++j) {
        float4 s = S[lane + 32 * j];
        sum += __expf(s.x - mx) + __expf(s.y - mx)
             + __expf(s.z - mx) + __expf(s.w - mx);
    }
#pragma unroll
    for (int off = 16; off; off >>= 1)
        sum += __shfl_xor_sync(0xffffffffu, sum, off);

    if (lane == 0) { g_m[row] = mx; g_sum[row] = sum; }
}

// ---------------------------------------------------------------------------
// PV partial: block = 32 q-rows x 256-k slice. Grid = 32 * 8 = 256.
// Writes unnormalized partials to g_part[ks][q][d].
// ---------------------------------------------------------------------------
__global__ __launch_bounds__(256) void pv_kernel(
    const float* __restrict__ value, const float* __restrict__ scores)
{
    __shared__ __align__(16) float Vs[64 * 68];   // [d][k]
    __shared__ __align__(16) float Es[32 * 68];   // [q][k]

    const int t = threadIdx.x;
    const int qt = blockIdx.x >> 3, ks = blockIdx.x & 7;
    const int qb = qt * 32, kb = ks * 256;

    const int erow = t >> 3, ecol = (t & 7) * 8;   // E fill: 8 exps/thread/iter
    const float mE = g_m[qb + erow];
    const int vd = t >> 4, vk = (t & 15) * 4;      // V fill
    const int dC = t & 63, qg = t >> 6;            // compute

    ull acc[8];
#pragma unroll
    for (int j = 0; j < 8; ++j) acc[j] = 0ULL;

    for (int it = 0; it < 4; ++it) {
        const int kt = kb + it * 64;
#pragma unroll
        for (int c = 0; c < 2; ++c) {
            float4 s = *reinterpret_cast<const float4*>(
                &scores[(qb + erow) * NK + kt + ecol + 4 * c]);
            float4 e;
            e.x = __expf(s.x - mE); e.y = __expf(s.y - mE);
            e.z = __expf(s.z - mE); e.w = __expf(s.w - mE);
            *reinterpret_cast<float4*>(&Es[erow * 68 + ecol + 4 * c]) = e;
        }
#pragma unroll
        for (int r = 0; r < 4; ++r) {
            int d = vd + 16 * r;
            *reinterpret_cast<float4*>(&Vs[d * 68 + vk]) =
                *reinterpret_cast<const float4*>(&value[d * NK + kt + vk]);
        }
        __syncthreads();

        const float4* V4 = reinterpret_cast<const float4*>(&Vs[dC * 68]);
#pragma unroll
        for (int kk = 0; kk < 16; ++kk) {
            float4 v = V4[kk];
            ull v01 = packf2(v.x, v.y), v23 = packf2(v.z, v.w);
#pragma unroll
            for (int j = 0; j < 8; ++j) {
                float4 e = *reinterpret_cast<const float4*>(
                    &Es[(qg * 8 + j) * 68 + 4 * kk]);
                acc[j] = fmax2(packf2(e.x, e.y), v01, acc[j]);
                acc[j] = fmax2(packf2(e.z, e.w), v23, acc[j]);
            }
        }
        __syncthreads();
    }

#pragma unroll
    for (int j = 0; j < 8; ++j) {
        float2 p = unpackf2(acc[j]);
        g_part[ks * (NQ * DD) + (qb + qg * 8 + j) * DD + dC] = p.x + p.y;
    }
}

// ---------------------------------------------------------------------------
// Reduce partials over 8 k-splits, normalize, write out[d][q]. Grid 256.
// ---------------------------------------------------------------------------
__global__ __launch_bounds__(256) void reduce_kernel(float* __restrict__ out)
{
    const int idx = blockIdx.x * 256 + threadIdx.x;   // < 65536
    const int q = idx >> 6, d = idx & 63;
    float o = 0.f;
#pragma unroll
    for (int s = 0; s < 8; ++s)
        o += g_part[s * (NQ * DD) + (q << 6) + d];
    out[d * NQ + q] = o / g_sum[q];
}

// ---------------------------------------------------------------------------
extern "C" void kernel_launch(void* const* d_in, const int* in_sizes, int n_in,
                              void* d_out, int out_size)
{
    const float* query = (const float*)d_in[0];   // [1,64,1024]
    const float* key   = (const float*)d_in[1];   // [1,64,2048]
    const float* value = (const float*)d_in[2];   // [1,64,2048]
    const float* W1    = (const float*)d_in[3];   // [64,128]
    const float* b1    = (const float*)d_in[4];   // [64]
    const float* W2    = (const float*)d_in[5];   // [1,64]
    const float* b2    = (const float*)d_in[6];   // [1]

    float* out    = (float*)d_out;                // [1,64,1024]
    float* scores = out + DD * NQ;                // [1,1024,2048]

    proj_kernel<<<NQ / 16 + NK / 16, 256>>>(query, key, W1, b1);
    scores_kernel<<<(NQ / 64) * (NK / 64), 256>>>(W2, b2, scores);
    rowstat_kernel<<<NQ / 8, 256>>>(scores);
    pv_kernel<<<(NQ / 32) * (NK / 256), 256>>>(value, scores);
    reduce_kernel<<<NQ * DD / 256, 256>>>(out);
}

// round 11
// speedup vs baseline: 1.4426x; 1.1958x over previous
#include <cuda_runtime.h>

typedef unsigned long long ull;

#define NQ 1024
#define NK 2048
#define DD 64
#define KSPLIT 16          // pv k-splits (NK/128)

// Scratch (static device globals — no allocation).
__device__ float g_qpT[DD * NQ];            // [h][q], b1 folded in
__device__ float g_kpT[DD * NK];            // [h][k]
__device__ ull   g_w2d[DD];                 // packed (w,w)
__device__ float g_ml[KSPLIT * NQ];         // slice-local max
__device__ float g_sl[KSPLIT * NQ];         // slice-local expsum
__device__ float g_part[KSPLIT * NQ * DD];  // pv partials [ks][q][d]

// ---- f32x2 helpers ----
__device__ __forceinline__ ull addx2(ull a, ull b) {
    ull d; asm("add.rn.f32x2 %0,%1,%2;" : "=l"(d) : "l"(a), "l"(b)); return d;
}
__device__ __forceinline__ ull fmax2(ull a, ull b, ull c) {
    ull d; asm("fma.rn.f32x2 %0,%1,%2,%3;" : "=l"(d) : "l"(a), "l"(b), "l"(c)); return d;
}
__device__ __forceinline__ ull packf2(float lo, float hi) {
    ull d; asm("mov.b64 %0,{%1,%2};" : "=l"(d)
               : "r"(__float_as_uint(lo)), "r"(__float_as_uint(hi))); return d;
}
__device__ __forceinline__ float2 unpackf2(ull x) {
    unsigned lo, hi; asm("mov.b64 {%0,%1},%2;" : "=r"(lo), "=r"(hi) : "l"(x));
    return make_float2(__uint_as_float(lo), __uint_as_float(hi));
}
// relu on both halves: 2x FMNMX (alu pipe); pack/unpack are register aliasing.
__device__ __forceinline__ ull relu2(ull x) {
    float2 f = unpackf2(x);
    f.x = fmaxf(f.x, 0.f); f.y = fmaxf(f.y, 0.f);
    return packf2(f.x, f.y);
}

// ---------------------------------------------------------------------------
// Projection, 16-row tiles. Grid = 64 (q) + 128 (k) = 192 blocks.
// Block 0 additionally packs W2 into g_w2d.
// ---------------------------------------------------------------------------
__global__ __launch_bounds__(256) void proj_kernel(
    const float* __restrict__ q_in, const float* __restrict__ k_in,
    const float* __restrict__ W1, const float* __restrict__ b1,
    const float* __restrict__ W2)
{
    __shared__ __align__(16) float srcS[16 * 68];  // [c][d]
    __shared__ __align__(16) float wS[64 * 68];    // [h][d]
    __shared__ float oS[64 * 17];                  // [h][c]

    const int t = threadIdx.x;
    if (blockIdx.x == 0 && t < 64) { float w = W2[t]; g_w2d[t] = packf2(w, w); }

    const bool isQ = blockIdx.x < (NQ / 16);
    const int row0 = isQ ? blockIdx.x * 16 : (blockIdx.x - NQ / 16) * 16;
    const float* src = isQ ? q_in : k_in;
    const int stride = isQ ? NQ : NK;
    const int wOff = isQ ? 0 : DD;
    float* dstT = isQ ? g_qpT : g_kpT;

#pragma unroll
    for (int r = 0; r < 4; ++r) {
        int i = t + 256 * r;
        int d = i >> 4, c = i & 15;
        srcS[c * 68 + d] = src[d * stride + row0 + c];
    }
#pragma unroll
    for (int r = 0; r < 16; ++r) {
        int i = t + 256 * r;
        int h = i >> 6, d = i & 63;
        wS[h * 68 + d] = W1[h * 128 + wOff + d];
    }
    __syncthreads();

    const int h = t & 63;
    const int c0 = t >> 6;
    float acc[4] = {0.f, 0.f, 0.f, 0.f};
    const float4* w4 = reinterpret_cast<const float4*>(&wS[h * 68]);
#pragma unroll
    for (int d4 = 0; d4 < 16; ++d4) {
        float4 w = w4[d4];
#pragma unroll
        for (int j = 0; j < 4; ++j) {
            float4 s = *reinterpret_cast<const float4*>(&srcS[(c0 + 4 * j) * 68 + 4 * d4]);
            acc[j] += w.x * s.x + w.y * s.y + w.z * s.z + w.w * s.w;
        }
    }
    float bias = isQ ? b1[h] : 0.f;
#pragma unroll
    for (int j = 0; j < 4; ++j) oS[h * 17 + c0 + 4 * j] = acc[j] + bias;
    __syncthreads();
#pragma unroll
    for (int r = 0; r < 4; ++r) {
        int i = t + 256 * r;
        int hh = i >> 4, c = i & 15;
        dstT[hh * stride + row0 + c] = oS[hh * 17 + c];
    }
}

// ---------------------------------------------------------------------------
// Scores: 64q x 64k per block, 4q x 4k per thread, packed over q.
// Per pair: FADD2 + 2xFMNMX(alu) + FFMA2. k duplicated in smem. Grid 512.
// ---------------------------------------------------------------------------
__global__ __launch_bounds__(256) void scores_kernel(
    const float* __restrict__ b2, float* __restrict__ scores)
{
    __shared__ __align__(16) float qpS[64 * 64];   // [h][q]   16KB
    __shared__ __align__(16) float kpD[64 * 128];  // [h][2k] duped  32KB

    const int t = threadIdx.x;
    const int kb = (blockIdx.x & 31) * 64;
    const int qb = (blockIdx.x >> 5) * 64;

#pragma unroll
    for (int r = 0; r < 4; ++r) {
        int i = t + 256 * r;                 // float4 idx < 1024
        int h = i >> 4, off = (i & 15) * 4;
        *reinterpret_cast<float4*>(&qpS[h * 64 + off]) =
            *reinterpret_cast<const float4*>(&g_qpT[h * NQ + qb + off]);
        float4 v = *reinterpret_cast<const float4*>(&g_kpT[h * NK + kb + off]);
        float4 lo = {v.x, v.x, v.y, v.y};
        float4 hi = {v.z, v.z, v.w, v.w};
        *reinterpret_cast<float4*>(&kpD[h * 128 + 2 * off]) = lo;
        *reinterpret_cast<float4*>(&kpD[h * 128 + 2 * off + 4]) = hi;
    }
    const float b2v = b2[0];
    __syncthreads();

    const int kg = t & 15, qg = t >> 4;
    const int q0 = 4 * qg;

    ull acc[2][4];
#pragma unroll
    for (int p = 0; p < 2; ++p)
#pragma unroll
        for (int j = 0; j < 4; ++j) acc[p][j] = 0ULL;

#pragma unroll 4
    for (int h = 0; h < 64; ++h) {
        ulonglong2 a = *reinterpret_cast<const ulonglong2*>(&qpS[h * 64 + q0]);
        ull w2 = g_w2d[h];
#pragma unroll
        for (int j = 0; j < 4; ++j) {
            ull kd = *reinterpret_cast<const ull*>(&kpD[h * 128 + 2 * (kg + 16 * j)]);
            acc[0][j] = fmax2(w2, relu2(addx2(a.x, kd)), acc[0][j]);
            acc[1][j] = fmax2(w2, relu2(addx2(a.y, kd)), acc[1][j]);
        }
    }

#pragma unroll
    for (int p = 0; p < 2; ++p)
#pragma unroll
        for (int j = 0; j < 4; ++j) {
            float2 u = unpackf2(acc[p][j]);
            int k = kg + 16 * j;
            scores[(qb + q0 + 2 * p) * NK + kb + k] = u.x + b2v;
            scores[(qb + q0 + 2 * p + 1) * NK + kb + k] = u.y + b2v;
        }
}

// ---------------------------------------------------------------------------
// PV: block = 32q x 128k slice, flash-local softmax + GEMM. Grid 32*16 = 512.
// Es[32][128] exp'd in place; Vs[64][128] XOR-swizzled (kw ^ 4*(d&7)).
// Microtile 4q x 2d packed over k. Exactly 48KB static smem.
// ---------------------------------------------------------------------------
__global__ __launch_bounds__(256) void pv_kernel(
    const float* __restrict__ value, const float* __restrict__ scores)
{
    __shared__ __align__(16) float Es[32 * 128];
    __shared__ __align__(16) float Vs[64 * 128];

    const int t = threadIdx.x;
    const int qt = blockIdx.x >> 4, ks = blockIdx.x & 15;
    const int qb = qt * 32, kb = ks * 128;

    // ---- stage A: load slice scores, slice max, exp, sum ----
    const int row = t >> 3, l8 = t & 7;
    float sv[16];
    float mx = -3.0e38f;
#pragma unroll
    for (int j = 0; j < 4; ++j) {
        float4 s = *reinterpret_cast<const float4*>(
            &scores[(qb + row) * NK + kb + 4 * l8 + 32 * j]);
        sv[4 * j] = s.x; sv[4 * j + 1] = s.y; sv[4 * j + 2] = s.z; sv[4 * j + 3] = s.w;
        mx = fmaxf(mx, fmaxf(fmaxf(s.x, s.y), fmaxf(s.z, s.w)));
    }
#pragma unroll
    for (int off = 4; off; off >>= 1)
        mx = fmaxf(mx, __shfl_xor_sync(0xffffffffu, mx, off));
    float sum = 0.f;
#pragma unroll
    for (int j = 0; j < 4; ++j) {
        float4 e;
        e.x = __expf(sv[4 * j] - mx);     e.y = __expf(sv[4 * j + 1] - mx);
        e.z = __expf(sv[4 * j + 2] - mx); e.w = __expf(sv[4 * j + 3] - mx);
        sum += (e.x + e.y) + (e.z + e.w);
        *reinterpret_cast<float4*>(&Es[row * 128 + 4 * l8 + 32 * j]) = e;
    }
#pragma unroll
    for (int off = 4; off; off >>= 1)
        sum += __shfl_xor_sync(0xffffffffu, sum, off);
    if (l8 == 0) { g_ml[ks * NQ + qb + row] = mx; g_sl[ks * NQ + qb + row] = sum; }

    // ---- stage B: V tile, swizzled ----
#pragma unroll
    for (int r = 0; r < 8; ++r) {
        int i = t + 256 * r;                // float4 idx < 2048
        int d = i >> 5, c4 = (i & 31) * 4;
        float4 v = *reinterpret_cast<const float4*>(&value[d * NK + kb + c4]);
        *reinterpret_cast<float4*>(&Vs[d * 128 + (c4 ^ ((d & 7) << 2))]) = v;
    }
    __syncthreads();

    // ---- GEMM: 4q x 2d per thread, packed over k, no syncs ----
    const int qg = t >> 5, dg = t & 31;     // warp-uniform qg
    const int q0 = 4 * qg;
    const int xsw = (dg & 7) << 2;
    const float* VA = &Vs[dg * 128];
    const float* VB = &Vs[(dg + 32) * 128];

    ull acc[4][2];
#pragma unroll
    for (int i = 0; i < 4; ++i) { acc[i][0] = 0ULL; acc[i][1] = 0ULL; }

#pragma unroll 2
    for (int kk = 0; kk < 32; ++kk) {
        const int kw = 4 * kk;
        const int kwx = kw ^ xsw;
        ulonglong2 v0 = *reinterpret_cast<const ulonglong2*>(&VA[kwx]);
        ulonglong2 v1 = *reinterpret_cast<const ulonglong2*>(&VB[kwx]);
        ulonglong2 e0 = *reinterpret_cast<const ulonglong2*>(&Es[(q0 + 0) * 128 + kw]);
        ulonglong2 e1 = *reinterpret_cast<const ulonglong2*>(&Es[(q0 + 1) * 128 + kw]);
        ulonglong2 e2 = *reinterpret_cast<const ulonglong2*>(&Es[(q0 + 2) * 128 + kw]);
        ulonglong2 e3 = *reinterpret_cast<const ulonglong2*>(&Es[(q0 + 3) * 128 + kw]);
        acc[0][0] = fmax2(e0.x, v0.x, acc[0][0]); acc[0][0] = fmax2(e0.y, v0.y, acc[0][0]);
        acc[1][0] = fmax2(e1.x, v0.x, acc[1][0]); acc[1][0] = fmax2(e1.y, v0.y, acc[1][0]);
        acc[2][0] = fmax2(e2.x, v0.x, acc[2][0]); acc[2][0] = fmax2(e2.y, v0.y, acc[2][0]);
        acc[3][0] = fmax2(e3.x, v0.x, acc[3][0]); acc[3][0] = fmax2(e3.y, v0.y, acc[3][0]);
        acc[0][1] = fmax2(e0.x, v1.x, acc[0][1]); acc[0][1] = fmax2(e0.y, v1.y, acc[0][1]);
        acc[1][1] = fmax2(e1.x, v1.x, acc[1][1]); acc[1][1] = fmax2(e1.y, v1.y, acc[1][1]);
        acc[2][1] = fmax2(e2.x, v1.x, acc[2][1]); acc[2][1] = fmax2(e2.y, v1.y, acc[2][1]);
        acc[3][1] = fmax2(e3.x, v1.x, acc[3][1]); acc[3][1] = fmax2(e3.y, v1.y, acc[3][1]);
    }

#pragma unroll
    for (int i = 0; i < 4; ++i)
#pragma unroll
        for (int j = 0; j < 2; ++j) {
            float2 u = unpackf2(acc[i][j]);
            g_part[ks * (NQ * DD) + (qb + q0 + i) * DD + dg + 32 * j] = u.x + u.y;
        }
}

// ---------------------------------------------------------------------------
// Flash-merge reduce: combine 16 k-splits, normalize, write out[d][q].
// ---------------------------------------------------------------------------
__global__ __launch_bounds__(256) void reduce_kernel(float* __restrict__ out)
{
    const int idx = blockIdx.x * 256 + threadIdx.x;   // < 65536
    const int q = idx >> 6, d = idx & 63;

    float M = -3.0e38f;
#pragma unroll
    for (int s = 0; s < KSPLIT; ++s) M = fmaxf(M, g_ml[s * NQ + q]);

    float o = 0.f, S = 0.f;
#pragma unroll
    for (int s = 0; s < KSPLIT; ++s) {
        float f = __expf(g_ml[s * NQ + q] - M);
        o += g_part[s * (NQ * DD) + q * DD + d] * f;
        S += g_sl[s * NQ + q] * f;
    }
    out[d * NQ + q] = o / S;
}

// ---------------------------------------------------------------------------
extern "C" void kernel_launch(void* const* d_in, const int* in_sizes, int n_in,
                              void* d_out, int out_size)
{
    const float* query = (const float*)d_in[0];   // [1,64,1024]
    const float* key   = (const float*)d_in[1];   // [1,64,2048]
    const float* value = (const float*)d_in[2];   // [1,64,2048]
    const float* W1    = (const float*)d_in[3];   // [64,128]
    const float* b1    = (const float*)d_in[4];   // [64]
    const float* W2    = (const float*)d_in[5];   // [1,64]
    const float* b2    = (const float*)d_in[6];   // [1]

    float* out    = (float*)d_out;                // [1,64,1024]
    float* scores = out + DD * NQ;                // [1,1024,2048]

    proj_kernel<<<NQ / 16 + NK / 16, 256>>>(query, key, W1, b1, W2);
    scores_kernel<<<(NQ / 64) * (NK / 64), 256>>>(b2, scores);
    pv_kernel<<<(NQ / 32) * (NK / 128), 256>>>(value, scores);
    reduce_kernel<<<NQ * DD / 256, 256>>>(out);
}

// round 12
// speedup vs baseline: 1.4437x; 1.0008x over previous
#include <cuda_runtime.h>

typedef unsigned long long ull;

#define NQ 1024
#define NK 2048
#define DD 64
#define KSPLIT 16          // pv k-splits (NK/128)

// Scratch (static device globals — no allocation).
__device__ float g_qpT[DD * NQ];            // [h][q], b1 folded in
__device__ float g_kpT[DD * NK];            // [h][k]
__device__ ull   g_w2d[DD];                 // packed (w,w)
__device__ float g_ml[KSPLIT * NQ];         // slice-local max
__device__ float g_sl[KSPLIT * NQ];         // slice-local expsum
__device__ float g_F[KSPLIT * NQ];          // merge factor exp(ml-M)/S
__device__ float g_part[KSPLIT * DD * NQ];  // pv partials [ks][d][q]

// ---- f32x2 helpers ----
__device__ __forceinline__ ull addx2(ull a, ull b) {
    ull d; asm("add.rn.f32x2 %0,%1,%2;" : "=l"(d) : "l"(a), "l"(b)); return d;
}
__device__ __forceinline__ ull fmax2(ull a, ull b, ull c) {
    ull d; asm("fma.rn.f32x2 %0,%1,%2,%3;" : "=l"(d) : "l"(a), "l"(b), "l"(c)); return d;
}
__device__ __forceinline__ ull packf2(float lo, float hi) {
    ull d; asm("mov.b64 %0,{%1,%2};" : "=l"(d)
               : "r"(__float_as_uint(lo)), "r"(__float_as_uint(hi))); return d;
}
__device__ __forceinline__ float2 unpackf2(ull x) {
    unsigned lo, hi; asm("mov.b64 {%0,%1},%2;" : "=r"(lo), "=r"(hi) : "l"(x));
    return make_float2(__uint_as_float(lo), __uint_as_float(hi));
}
__device__ __forceinline__ ull relu2(ull x) {
    float2 f = unpackf2(x);
    f.x = fmaxf(f.x, 0.f); f.y = fmaxf(f.y, 0.f);
    return packf2(f.x, f.y);
}

// ---------------------------------------------------------------------------
// Projection, 16-row tiles. Grid = 64 (q) + 128 (k) = 192 blocks.
// Block 0 additionally packs W2 into g_w2d.
// ---------------------------------------------------------------------------
__global__ __launch_bounds__(256) void proj_kernel(
    const float* __restrict__ q_in, const float* __restrict__ k_in,
    const float* __restrict__ W1, const float* __restrict__ b1,
    const float* __restrict__ W2)
{
    __shared__ __align__(16) float srcS[16 * 68];  // [c][d]
    __shared__ __align__(16) float wS[64 * 68];    // [h][d]
    __shared__ float oS[64 * 17];                  // [h][c]

    const int t = threadIdx.x;
    if (blockIdx.x == 0 && t < 64) { float w = W2[t]; g_w2d[t] = packf2(w, w); }

    const bool isQ = blockIdx.x < (NQ / 16);
    const int row0 = isQ ? blockIdx.x * 16 : (blockIdx.x - NQ / 16) * 16;
    const float* src = isQ ? q_in : k_in;
    const int stride = isQ ? NQ : NK;
    const int wOff = isQ ? 0 : DD;
    float* dstT = isQ ? g_qpT : g_kpT;

#pragma unroll
    for (int r = 0; r < 4; ++r) {
        int i = t + 256 * r;
        int d = i >> 4, c = i & 15;
        srcS[c * 68 + d] = src[d * stride + row0 + c];
    }
#pragma unroll
    for (int r = 0; r < 16; ++r) {
        int i = t + 256 * r;
        int h = i >> 6, d = i & 63;
        wS[h * 68 + d] = W1[h * 128 + wOff + d];
    }
    __syncthreads();

    const int h = t & 63;
    const int c0 = t >> 6;
    float acc[4] = {0.f, 0.f, 0.f, 0.f};
    const float4* w4 = reinterpret_cast<const float4*>(&wS[h * 68]);
#pragma unroll
    for (int d4 = 0; d4 < 16; ++d4) {
        float4 w = w4[d4];
#pragma unroll
        for (int j = 0; j < 4; ++j) {
            float4 s = *reinterpret_cast<const float4*>(&srcS[(c0 + 4 * j) * 68 + 4 * d4]);
            acc[j] += w.x * s.x + w.y * s.y + w.z * s.z + w.w * s.w;
        }
    }
    float bias = isQ ? b1[h] : 0.f;
#pragma unroll
    for (int j = 0; j < 4; ++j) oS[h * 17 + c0 + 4 * j] = acc[j] + bias;
    __syncthreads();
#pragma unroll
    for (int r = 0; r < 4; ++r) {
        int i = t + 256 * r;
        int hh = i >> 4, c = i & 15;
        dstT[hh * stride + row0 + c] = oS[hh * 17 + c];
    }
}

// ---------------------------------------------------------------------------
// Scores: 64q x 64k per block, 4q x 4k per thread, packed over q. Grid 512.
// ---------------------------------------------------------------------------
__global__ __launch_bounds__(256) void scores_kernel(
    const float* __restrict__ b2, float* __restrict__ scores)
{
    __shared__ __align__(16) float qpS[64 * 64];   // [h][q]   16KB
    __shared__ __align__(16) float kpD[64 * 128];  // [h][2k] duped  32KB

    const int t = threadIdx.x;
    const int kb = (blockIdx.x & 31) * 64;
    const int qb = (blockIdx.x >> 5) * 64;

#pragma unroll
    for (int r = 0; r < 4; ++r) {
        int i = t + 256 * r;                 // float4 idx < 1024
        int h = i >> 4, off = (i & 15) * 4;
        *reinterpret_cast<float4*>(&qpS[h * 64 + off]) =
            *reinterpret_cast<const float4*>(&g_qpT[h * NQ + qb + off]);
        float4 v = *reinterpret_cast<const float4*>(&g_kpT[h * NK + kb + off]);
        float4 lo = {v.x, v.x, v.y, v.y};
        float4 hi = {v.z, v.z, v.w, v.w};
        *reinterpret_cast<float4*>(&kpD[h * 128 + 2 * off]) = lo;
        *reinterpret_cast<float4*>(&kpD[h * 128 + 2 * off + 4]) = hi;
    }
    const float b2v = b2[0];
    __syncthreads();

    const int kg = t & 15, qg = t >> 4;
    const int q0 = 4 * qg;

    ull acc[2][4];
#pragma unroll
    for (int p = 0; p < 2; ++p)
#pragma unroll
        for (int j = 0; j < 4; ++j) acc[p][j] = 0ULL;

#pragma unroll 4
    for (int h = 0; h < 64; ++h) {
        ulonglong2 a = *reinterpret_cast<const ulonglong2*>(&qpS[h * 64 + q0]);
        ull w2 = g_w2d[h];
#pragma unroll
        for (int j = 0; j < 4; ++j) {
            ull kd = *reinterpret_cast<const ull*>(&kpD[h * 128 + 2 * (kg + 16 * j)]);
            acc[0][j] = fmax2(w2, relu2(addx2(a.x, kd)), acc[0][j]);
            acc[1][j] = fmax2(w2, relu2(addx2(a.y, kd)), acc[1][j]);
        }
    }

#pragma unroll
    for (int p = 0; p < 2; ++p)
#pragma unroll
        for (int j = 0; j < 4; ++j) {
            float2 u = unpackf2(acc[p][j]);
            int k = kg + 16 * j;
            scores[(qb + q0 + 2 * p) * NK + kb + k] = u.x + b2v;
            scores[(qb + q0 + 2 * p + 1) * NK + kb + k] = u.y + b2v;
        }
}

// ---------------------------------------------------------------------------
// PV: block = 32q x 128k slice, 128 threads, 8q x 2d microtile. Grid 512.
// Es[32][128] exp'd scores; Vs[64][128] XOR-swizzled. 48KB static smem.
// Partials written [ks][d][q] (coalesced) via smem transpose reusing Es.
// ---------------------------------------------------------------------------
__global__ __launch_bounds__(128) void pv_kernel(
    const float* __restrict__ value, const float* __restrict__ scores)
{
    __shared__ __align__(16) float Es[32 * 128];
    __shared__ __align__(16) float Vs[64 * 128];

    const int t = threadIdx.x;
    const int qt = blockIdx.x >> 4, ks = blockIdx.x & 15;
    const int qb = qt * 32, kb = ks * 128;

    // ---- stage A: slice scores -> max -> exp -> sum (4 threads/row) ----
    const int row = t >> 2, l4 = t & 3;
    float sv[32];
    float mx = -3.0e38f;
#pragma unroll
    for (int j = 0; j < 8; ++j) {
        float4 s = *reinterpret_cast<const float4*>(
            &scores[(qb + row) * NK + kb + 4 * l4 + 16 * j]);
        sv[4 * j] = s.x; sv[4 * j + 1] = s.y; sv[4 * j + 2] = s.z; sv[4 * j + 3] = s.w;
        mx = fmaxf(mx, fmaxf(fmaxf(s.x, s.y), fmaxf(s.z, s.w)));
    }
    mx = fmaxf(mx, __shfl_xor_sync(0xffffffffu, mx, 2, 4));
    mx = fmaxf(mx, __shfl_xor_sync(0xffffffffu, mx, 1, 4));
    float sum = 0.f;
#pragma unroll
    for (int j = 0; j < 8; ++j) {
        float4 e;
        e.x = __expf(sv[4 * j] - mx);     e.y = __expf(sv[4 * j + 1] - mx);
        e.z = __expf(sv[4 * j + 2] - mx); e.w = __expf(sv[4 * j + 3] - mx);
        sum += (e.x + e.y) + (e.z + e.w);
        *reinterpret_cast<float4*>(&Es[row * 128 + 4 * l4 + 16 * j]) = e;
    }
    sum += __shfl_xor_sync(0xffffffffu, sum, 2, 4);
    sum += __shfl_xor_sync(0xffffffffu, sum, 1, 4);
    if (l4 == 0) { g_ml[ks * NQ + qb + row] = mx; g_sl[ks * NQ + qb + row] = sum; }

    // ---- stage B: V tile, swizzled ----
#pragma unroll
    for (int r = 0; r < 16; ++r) {
        int i = t + 128 * r;                // float4 idx < 2048
        int d = i >> 5, c4 = (i & 31) * 4;
        float4 v = *reinterpret_cast<const float4*>(&value[d * NK + kb + c4]);
        *reinterpret_cast<float4*>(&Vs[d * 128 + (c4 ^ ((d & 7) << 2))]) = v;
    }
    __syncthreads();

    // ---- GEMM: 8q x 2d per thread, packed over k ----
    const int qg = t >> 5, dg = t & 31;
    const int q0 = 8 * qg;
    const int xsw = (dg & 7) << 2;
    const float* VA = &Vs[dg * 128];
    const float* VB = &Vs[(dg + 32) * 128];

    ull acc[8][2];
#pragma unroll
    for (int i = 0; i < 8; ++i) { acc[i][0] = 0ULL; acc[i][1] = 0ULL; }

#pragma unroll 4
    for (int kk = 0; kk < 32; ++kk) {
        const int kw = 4 * kk;
        const int kwx = kw ^ xsw;
        ulonglong2 v0 = *reinterpret_cast<const ulonglong2*>(&VA[kwx]);
        ulonglong2 v1 = *reinterpret_cast<const ulonglong2*>(&VB[kwx]);
#pragma unroll
        for (int i = 0; i < 8; ++i) {
            ulonglong2 e = *reinterpret_cast<const ulonglong2*>(&Es[(q0 + i) * 128 + kw]);
            acc[i][0] = fmax2(e.x, v0.x, acc[i][0]);
            acc[i][0] = fmax2(e.y, v0.y, acc[i][0]);
            acc[i][1] = fmax2(e.x, v1.x, acc[i][1]);
            acc[i][1] = fmax2(e.y, v1.y, acc[i][1]);
        }
    }
    __syncthreads();

    // ---- epilogue: transpose via smem (reuse Es), write part[ks][d][q] ----
    float* EsT = Es;                        // [64][33]
#pragma unroll
    for (int i = 0; i < 8; ++i)
#pragma unroll
        for (int j = 0; j < 2; ++j) {
            float2 u = unpackf2(acc[i][j]);
            EsT[(dg + 32 * j) * 33 + q0 + i] = u.x + u.y;
        }
    __syncthreads();
#pragma unroll
    for (int r = 0; r < 16; ++r) {
        int i = t + 128 * r;                // < 2048
        int d = i >> 5, qq = i & 31;
        g_part[ks * (DD * NQ) + d * NQ + qb + qq] = EsT[d * 33 + qq];
    }
}

// ---------------------------------------------------------------------------
// Factor: F[s][q] = exp(ml - M) / S, S = sum_s sl*exp(ml - M). Grid 64.
// 16 s-lanes per q in a half-warp group.
// ---------------------------------------------------------------------------
__global__ __launch_bounds__(256) void factor_kernel()
{
    const int t = threadIdx.x;
    const int s = t & 15;
    const int q = blockIdx.x * 16 + (t >> 4);

    float ml = g_ml[s * NQ + q];
    float M = ml;
    M = fmaxf(M, __shfl_xor_sync(0xffffffffu, M, 8, 16));
    M = fmaxf(M, __shfl_xor_sync(0xffffffffu, M, 4, 16));
    M = fmaxf(M, __shfl_xor_sync(0xffffffffu, M, 2, 16));
    M = fmaxf(M, __shfl_xor_sync(0xffffffffu, M, 1, 16));
    float f = __expf(ml - M);
    float p = g_sl[s * NQ + q] * f;
    p += __shfl_xor_sync(0xffffffffu, p, 8, 16);
    p += __shfl_xor_sync(0xffffffffu, p, 4, 16);
    p += __shfl_xor_sync(0xffffffffu, p, 2, 16);
    p += __shfl_xor_sync(0xffffffffu, p, 1, 16);
    g_F[s * NQ + q] = f / p;
}

// ---------------------------------------------------------------------------
// Reduce: out[d][q] = sum_s part[s][d][q] * F[s][q]. Fully coalesced. Grid 256.
// ---------------------------------------------------------------------------
__global__ __launch_bounds__(256) void reduce_kernel(float* __restrict__ out)
{
    const int idx = blockIdx.x * 256 + threadIdx.x;   // < 65536
    const int d = idx >> 10, q = idx & 1023;

    float o = 0.f;
#pragma unroll
    for (int s = 0; s < KSPLIT; ++s)
        o += g_part[s * (DD * NQ) + d * NQ + q] * g_F[s * NQ + q];
    out[d * NQ + q] = o;
}

// ---------------------------------------------------------------------------
extern "C" void kernel_launch(void* const* d_in, const int* in_sizes, int n_in,
                              void* d_out, int out_size)
{
    const float* query = (const float*)d_in[0];   // [1,64,1024]
    const float* key   = (const float*)d_in[1];   // [1,64,2048]
    const float* value = (const float*)d_in[2];   // [1,64,2048]
    const float* W1    = (const float*)d_in[3];   // [64,128]
    const float* b1    = (const float*)d_in[4];   // [64]
    const float* W2    = (const float*)d_in[5];   // [1,64]
    const float* b2    = (const float*)d_in[6];   // [1]

    float* out    = (float*)d_out;                // [1,64,1024]
    float* scores = out + DD * NQ;                // [1,1024,2048]

    proj_kernel<<<NQ / 16 + NK / 16, 256>>>(query, key, W1, b1, W2);
    scores_kernel<<<(NQ / 64) * (NK / 64), 256>>>(b2, scores);
    pv_kernel<<<(NQ / 32) * (NK / 128), 128>>>(value, scores);
    factor_kernel<<<NQ / 16, 256>>>();
    reduce_kernel<<<NQ * DD / 256, 256>>>(out);
}

// round 14
// speedup vs baseline: 1.4606x; 1.0117x over previous
#include <cuda_runtime.h>

typedef unsigned long long ull;

#define NQ 1024
#define NK 2048
#define DD 64
#define KSPLIT 16          // k-splits (NK/128)

// Scratch (static device globals — no allocation).
__device__ float g_qpT[DD * NQ];            // [h][q], b1 folded in
__device__ float g_kpT[DD * NK];            // [h][k]
__device__ ull   g_w2d[DD];                 // packed (w,w)
__device__ float g_ml[KSPLIT * NQ];         // slice-local max
__device__ float g_sl[KSPLIT * NQ];         // slice-local expsum
__device__ float g_part[KSPLIT * DD * NQ];  // pv partials [ks][d][q]

// ---- f32x2 helpers ----
__device__ __forceinline__ ull addx2(ull a, ull b) {
    ull d; asm("add.rn.f32x2 %0,%1,%2;" : "=l"(d) : "l"(a), "l"(b)); return d;
}
__device__ __forceinline__ ull fmax2(ull a, ull b, ull c) {
    ull d; asm("fma.rn.f32x2 %0,%1,%2,%3;" : "=l"(d) : "l"(a), "l"(b), "l"(c)); return d;
}
__device__ __forceinline__ ull packf2(float lo, float hi) {
    ull d; asm("mov.b64 %0,{%1,%2};" : "=l"(d)
               : "r"(__float_as_uint(lo)), "r"(__float_as_uint(hi))); return d;
}
__device__ __forceinline__ float2 unpackf2(ull x) {
    unsigned lo, hi; asm("mov.b64 {%0,%1},%2;" : "=r"(lo), "=r"(hi) : "l"(x));
    return make_float2(__uint_as_float(lo), __uint_as_float(hi));
}
__device__ __forceinline__ ull relu2(ull x) {
    float2 f = unpackf2(x);
    f.x = fmaxf(f.x, 0.f); f.y = fmaxf(f.y, 0.f);
    return packf2(f.x, f.y);
}

// ---------------------------------------------------------------------------
// Projection, 16-row tiles. Grid = 64 (q) + 128 (k) = 192 blocks.
// Block 0 additionally packs W2 into g_w2d.
// ---------------------------------------------------------------------------
__global__ __launch_bounds__(256) void proj_kernel(
    const float* __restrict__ q_in, const float* __restrict__ k_in,
    const float* __restrict__ W1, const float* __restrict__ b1,
    const float* __restrict__ W2)
{
    __shared__ __align__(16) float srcS[16 * 68];  // [c][d]
    __shared__ __align__(16) float wS[64 * 68];    // [h][d]
    __shared__ float oS[64 * 17];                  // [h][c]

    const int t = threadIdx.x;
    if (blockIdx.x == 0 && t < 64) { float w = W2[t]; g_w2d[t] = packf2(w, w); }

    const bool isQ = blockIdx.x < (NQ / 16);
    const int row0 = isQ ? blockIdx.x * 16 : (blockIdx.x - NQ / 16) * 16;
    const float* src = isQ ? q_in : k_in;
    const int stride = isQ ? NQ : NK;
    const int wOff = isQ ? 0 : DD;
    float* dstT = isQ ? g_qpT : g_kpT;

#pragma unroll
    for (int r = 0; r < 4; ++r) {
        int i = t + 256 * r;
        int d = i >> 4, c = i & 15;
        srcS[c * 68 + d] = src[d * stride + row0 + c];
    }
#pragma unroll
    for (int r = 0; r < 16; ++r) {
        int i = t + 256 * r;
        int h = i >> 6, d = i & 63;
        wS[h * 68 + d] = W1[h * 128 + wOff + d];
    }
    __syncthreads();

    const int h = t & 63;
    const int c0 = t >> 6;
    float acc[4] = {0.f, 0.f, 0.f, 0.f};
    const float4* w4 = reinterpret_cast<const float4*>(&wS[h * 68]);
#pragma unroll
    for (int d4 = 0; d4 < 16; ++d4) {
        float4 w = w4[d4];
#pragma unroll
        for (int j = 0; j < 4; ++j) {
            float4 s = *reinterpret_cast<const float4*>(&srcS[(c0 + 4 * j) * 68 + 4 * d4]);
            acc[j] += w.x * s.x + w.y * s.y + w.z * s.z + w.w * s.w;
        }
    }
    float bias = isQ ? b1[h] : 0.f;
#pragma unroll
    for (int j = 0; j < 4; ++j) oS[h * 17 + c0 + 4 * j] = acc[j] + bias;
    __syncthreads();
#pragma unroll
    for (int r = 0; r < 4; ++r) {
        int i = t + 256 * r;
        int hh = i >> 4, c = i & 15;
        dstT[hh * stride + row0 + c] = oS[hh * 17 + c];
    }
}

// ---------------------------------------------------------------------------
// Fused scores + softmax + PV-partial. Block = 32q x 128k. Grid 32*16 = 512.
// Phase 1: MLP scores (4q x 4k/thread, packed over k), raw scores -> gmem,
//          row max/exp/sum via warp shfl (warp == one 4q group).
// Phase 2: Es/Vs smem (reusing phase-1 region), 128-thread 8q x 2d GEMM,
//          transpose epilogue, coalesced part[ks][d][q] write.
// ---------------------------------------------------------------------------
__global__ __launch_bounds__(256) void fused_kernel(
    const float* __restrict__ value, const float* __restrict__ b2,
    float* __restrict__ scores)
{
    __shared__ __align__(16) char smbuf[49152];
    float* const qd = reinterpret_cast<float*>(smbuf);           // [64h][64] dup'd q
    float* const kp = reinterpret_cast<float*>(smbuf + 16384);   // [64h][128k]
    float* const Es = reinterpret_cast<float*>(smbuf);           // phase 2 [32q][128k]
    float* const Vs = reinterpret_cast<float*>(smbuf + 16384);   // phase 2 [64d][128k] swz

    const int t = threadIdx.x;
    const int qt = blockIdx.x >> 4, ks = blockIdx.x & 15;
    const int qb = qt * 32, kb = ks * 128;

    // ---- stage loads ----
#pragma unroll
    for (int r = 0; r < 8; ++r) {
        int i = t + 256 * r;                 // < 2048
        int h = i >> 5, qq = i & 31;
        float v = g_qpT[h * NQ + qb + qq];
        float2 dv = {v, v};
        *reinterpret_cast<float2*>(&qd[h * 64 + 2 * qq]) = dv;
    }
#pragma unroll
    for (int r = 0; r < 8; ++r) {
        int i = t + 256 * r;                 // float4 idx < 2048
        int h = i >> 5, c4 = (i & 31) * 4;
        *reinterpret_cast<float4*>(&kp[h * 128 + c4]) =
            *reinterpret_cast<const float4*>(&g_kpT[h * NK + kb + c4]);
    }
    __syncthreads();

    // ---- phase 1: MLP scores ----
    const int qg = t >> 5, kg = t & 31;      // warp == one qg
    const int q0 = 4 * qg, k0 = 4 * kg;

    ull acc[4][2];
#pragma unroll
    for (int i = 0; i < 4; ++i) { acc[i][0] = 0ULL; acc[i][1] = 0ULL; }

#pragma unroll 4
    for (int h = 0; h < 64; ++h) {
        ull w2 = g_w2d[h];                   // warp-uniform, L1 hit
        ulonglong2 kk_ = *reinterpret_cast<const ulonglong2*>(&kp[h * 128 + k0]);
#pragma unroll
        for (int i = 0; i < 4; ++i) {
            ull q2 = *reinterpret_cast<const ull*>(&qd[h * 64 + 2 * (q0 + i)]);
            acc[i][0] = fmax2(w2, relu2(addx2(q2, kk_.x)), acc[i][0]);
            acc[i][1] = fmax2(w2, relu2(addx2(q2, kk_.y)), acc[i][1]);
        }
    }

    const float b2v = b2[0];
    float s[4][4];
#pragma unroll
    for (int i = 0; i < 4; ++i) {
        float2 u0 = unpackf2(acc[i][0]);
        float2 u1 = unpackf2(acc[i][1]);
        s[i][0] = u0.x + b2v; s[i][1] = u0.y + b2v;
        s[i][2] = u1.x + b2v; s[i][3] = u1.y + b2v;
        float4 o = {s[i][0], s[i][1], s[i][2], s[i][3]};
        *reinterpret_cast<float4*>(&scores[(qb + q0 + i) * NK + kb + k0]) = o;
    }

    // row max (full-warp reductions; q0 uniform within warp)
    float mx[4];
#pragma unroll
    for (int i = 0; i < 4; ++i) {
        mx[i] = fmaxf(fmaxf(s[i][0], s[i][1]), fmaxf(s[i][2], s[i][3]));
#pragma unroll
        for (int off = 16; off; off >>= 1)
            mx[i] = fmaxf(mx[i], __shfl_xor_sync(0xffffffffu, mx[i], off));
    }
    // exp + row sum
    float e[4][4], sums[4];
#pragma unroll
    for (int i = 0; i < 4; ++i) {
        e[i][0] = __expf(s[i][0] - mx[i]); e[i][1] = __expf(s[i][1] - mx[i]);
        e[i][2] = __expf(s[i][2] - mx[i]); e[i][3] = __expf(s[i][3] - mx[i]);
        sums[i] = (e[i][0] + e[i][1]) + (e[i][2] + e[i][3]);
#pragma unroll
        for (int off = 16; off; off >>= 1)
            sums[i] += __shfl_xor_sync(0xffffffffu, sums[i], off);
    }
    if (kg == 0) {
#pragma unroll
        for (int i = 0; i < 4; ++i) {
            g_ml[ks * NQ + qb + q0 + i] = mx[i];
            g_sl[ks * NQ + qb + q0 + i] = sums[i];
        }
    }
    __syncthreads();                         // phase-1 smem now dead

    // ---- phase 2 staging: Es (exp'd) + Vs (swizzled) ----
#pragma unroll
    for (int i = 0; i < 4; ++i) {
        float4 o = {e[i][0], e[i][1], e[i][2], e[i][3]};
        *reinterpret_cast<float4*>(&Es[(q0 + i) * 128 + k0]) = o;
    }
#pragma unroll
    for (int r = 0; r < 8; ++r) {
        int i = t + 256 * r;                 // float4 idx < 2048
        int d = i >> 5, c4 = (i & 31) * 4;
        float4 v = *reinterpret_cast<const float4*>(&value[d * NK + kb + c4]);
        *reinterpret_cast<float4*>(&Vs[d * 128 + (c4 ^ ((d & 7) << 2))]) = v;
    }
    __syncthreads();

    // ---- GEMM: 128 threads, 8q x 2d per thread, packed over k ----
    ull a2[8][2];
    int dg = t & 31, q0b = 8 * (t >> 5);
    if (t < 128) {
        const int xsw = (dg & 7) << 2;
        const float* VA = &Vs[dg * 128];
        const float* VB = &Vs[(dg + 32) * 128];
#pragma unroll
        for (int i = 0; i < 8; ++i) { a2[i][0] = 0ULL; a2[i][1] = 0ULL; }
#pragma unroll 4
        for (int kk = 0; kk < 32; ++kk) {
            const int kw = 4 * kk;
            const int kwx = kw ^ xsw;
            ulonglong2 v0 = *reinterpret_cast<const ulonglong2*>(&VA[kwx]);
            ulonglong2 v1 = *reinterpret_cast<const ulonglong2*>(&VB[kwx]);
#pragma unroll
            for (int i = 0; i < 8; ++i) {
                ulonglong2 ee = *reinterpret_cast<const ulonglong2*>(&Es[(q0b + i) * 128 + kw]);
                a2[i][0] = fmax2(ee.x, v0.x, a2[i][0]);
                a2[i][0] = fmax2(ee.y, v0.y, a2[i][0]);
                a2[i][1] = fmax2(ee.x, v1.x, a2[i][1]);
                a2[i][1] = fmax2(ee.y, v1.y, a2[i][1]);
            }
        }
    }
    __syncthreads();

    // ---- epilogue: transpose via smem (reuse Es region as [64][33]) ----
    float* EsT = Es;
    if (t < 128) {
#pragma unroll
        for (int i = 0; i < 8; ++i)
#pragma unroll
            for (int j = 0; j < 2; ++j) {
                float2 u = unpackf2(a2[i][j]);
                EsT[(dg + 32 * j) * 33 + q0b + i] = u.x + u.y;
            }
    }
    __syncthreads();
#pragma unroll
    for (int r = 0; r < 8; ++r) {
        int i = t + 256 * r;                 // < 2048
        int d = i >> 5, qq = i & 31;
        g_part[ks * (DD * NQ) + d * NQ + qb + qq] = EsT[d * 33 + qq];
    }
}

// ---------------------------------------------------------------------------
// Reduce (+factor): block = 16 q-columns. F[s][q] in smem, then stream parts.
// Grid 64.
// ---------------------------------------------------------------------------
__global__ __launch_bounds__(256) void reduce_kernel(float* __restrict__ out)
{
    __shared__ float Fs[16 * 17];            // [s][q] padded

    const int t = threadIdx.x;
    const int qb = blockIdx.x * 16;

    // factor: t -> (s = t&15, q = t>>4); 16-lane group shfl reductions
    {
        const int s = t & 15, qq = t >> 4;
        float ml = g_ml[s * NQ + qb + qq];
        float M = ml;
        M = fmaxf(M, __shfl_xor_sync(0xffffffffu, M, 8, 16));
        M = fmaxf(M, __shfl_xor_sync(0xffffffffu, M, 4, 16));
        M = fmaxf(M, __shfl_xor_sync(0xffffffffu, M, 2, 16));
        M = fmaxf(M, __shfl_xor_sync(0xffffffffu, M, 1, 16));
        float f = __expf(ml - M);
        float p = g_sl[s * NQ + qb + qq] * f;
        p += __shfl_xor_sync(0xffffffffu, p, 8, 16);
        p += __shfl_xor_sync(0xffffffffu, p, 4, 16);
        p += __shfl_xor_sync(0xffffffffu, p, 2, 16);
        p += __shfl_xor_sync(0xffffffffu, p, 1, 16);
        Fs[s * 17 + qq] = f / p;
    }
    __syncthreads();

    // stream: 16q x 64d outputs, 4 d per thread
    const int q2 = t & 15, d0 = (t >> 4) * 4;
    float o[4] = {0.f, 0.f, 0.f, 0.f};
#pragma unroll
    for (int ss = 0; ss < KSPLIT; ++ss) {
        float F = Fs[ss * 17 + q2];
#pragma unroll
        for (int j = 0; j < 4; ++j)
            o[j] = fmaf(g_part[ss * (DD * NQ) + (d0 + j) * NQ + qb + q2], F, o[j]);
    }
#pragma unroll
    for (int j = 0; j < 4; ++j)
        out[(d0 + j) * NQ + qb + q2] = o[j];
}

// ---------------------------------------------------------------------------
extern "C" void kernel_launch(void* const* d_in, const int* in_sizes, int n_in,
                              void* d_out, int out_size)
{
    const float* query = (const float*)d_in[0];   // [1,64,1024]
    const float* key   = (const float*)d_in[1];   // [1,64,2048]
    const float* value = (const float*)d_in[2];   // [1,64,2048]
    const float* W1    = (const float*)d_in[3];   // [64,128]
    const float* b1    = (const float*)d_in[4];   // [64]
    const float* W2    = (const float*)d_in[5];   // [1,64]
    const float* b2    = (const float*)d_in[6];   // [1]

    float* out    = (float*)d_out;                // [1,64,1024]
    float* scores = out + DD * NQ;                // [1,1024,2048]

    proj_kernel<<<NQ / 16 + NK / 16, 256>>>(query, key, W1, b1, W2);
    fused_kernel<<<(NQ / 32) * (NK / 128), 256>>>(value, b2, scores);
    reduce_kernel<<<NQ / 16, 256>>>(out);
}

// round 15
// speedup vs baseline: 1.5101x; 1.0339x over previous
#include <cuda_runtime.h>

typedef unsigned long long ull;

#define NQ 1024
#define NK 2048
#define DD 64
#define KSPLIT 16          // k-splits (NK/128)

// Scratch (static device globals — no allocation).
__device__ float g_qpT[DD * NQ];            // [h][q], b1 folded in
__device__ float g_kpT[DD * NK];            // [h][k]
__device__ ull   g_w2d[DD];                 // packed (w,w)
__device__ float g_ml[KSPLIT * NQ];         // slice-local max
__device__ float g_sl[KSPLIT * NQ];         // slice-local expsum
__device__ float g_part[KSPLIT * DD * NQ];  // pv partials [ks][d][q]

// ---- f32x2 helpers ----
__device__ __forceinline__ ull addx2(ull a, ull b) {
    ull d; asm("add.rn.f32x2 %0,%1,%2;" : "=l"(d) : "l"(a), "l"(b)); return d;
}
__device__ __forceinline__ ull fmax2(ull a, ull b, ull c) {
    ull d; asm("fma.rn.f32x2 %0,%1,%2,%3;" : "=l"(d) : "l"(a), "l"(b), "l"(c)); return d;
}
__device__ __forceinline__ ull packf2(float lo, float hi) {
    ull d; asm("mov.b64 %0,{%1,%2};" : "=l"(d)
               : "r"(__float_as_uint(lo)), "r"(__float_as_uint(hi))); return d;
}
__device__ __forceinline__ float2 unpackf2(ull x) {
    unsigned lo, hi; asm("mov.b64 {%0,%1},%2;" : "=r"(lo), "=r"(hi) : "l"(x));
    return make_float2(__uint_as_float(lo), __uint_as_float(hi));
}
__device__ __forceinline__ ull relu2(ull x) {
    float2 f = unpackf2(x);
    f.x = fmaxf(f.x, 0.f); f.y = fmaxf(f.y, 0.f);
    return packf2(f.x, f.y);
}

// ---------------------------------------------------------------------------
// Projection: 32h x 16c tiles, 128 threads, grid = 192 col-tiles x 2 h-halves.
// Block 0 additionally packs W2 into g_w2d.
// ---------------------------------------------------------------------------
__global__ __launch_bounds__(128) void proj_kernel(
    const float* __restrict__ q_in, const float* __restrict__ k_in,
    const float* __restrict__ W1, const float* __restrict__ b1,
    const float* __restrict__ W2)
{
    __shared__ __align__(16) float srcS[16 * 68];  // [c][d]
    __shared__ __align__(16) float wS[32 * 68];    // [h][d]
    __shared__ float oS[32 * 17];                  // [h][c]

    const int t = threadIdx.x;
    const int bx = blockIdx.x;
    if (bx == 0 && t < 64) { float w = W2[t]; g_w2d[t] = packf2(w, w); }

    const int ct = bx >> 1, h0 = (bx & 1) * 32;
    const bool isQ = ct < (NQ / 16);
    const int row0 = isQ ? ct * 16 : (ct - NQ / 16) * 16;
    const float* src = isQ ? q_in : k_in;
    const int stride = isQ ? NQ : NK;
    const int wOff = isQ ? 0 : DD;
    float* dstT = isQ ? g_qpT : g_kpT;

#pragma unroll
    for (int r = 0; r < 8; ++r) {
        int i = t + 128 * r;                 // < 1024
        int d = i >> 4, c = i & 15;
        srcS[c * 68 + d] = src[d * stride + row0 + c];
    }
#pragma unroll
    for (int r = 0; r < 16; ++r) {
        int i = t + 128 * r;                 // < 2048
        int h = i >> 6, d = i & 63;
        wS[h * 68 + d] = W1[(h0 + h) * 128 + wOff + d];
    }
    __syncthreads();

    // microtile: h in {hg, hg+16}, c in {cg, cg+8}
    const int hg = t & 15, cg = t >> 4;      // cg 0..7
    float a00 = 0.f, a01 = 0.f, a10 = 0.f, a11 = 0.f;
#pragma unroll
    for (int d4 = 0; d4 < 16; ++d4) {
        float4 w0 = *reinterpret_cast<const float4*>(&wS[hg * 68 + 4 * d4]);
        float4 w1 = *reinterpret_cast<const float4*>(&wS[(hg + 16) * 68 + 4 * d4]);
        float4 s0 = *reinterpret_cast<const float4*>(&srcS[cg * 68 + 4 * d4]);
        float4 s1 = *reinterpret_cast<const float4*>(&srcS[(cg + 8) * 68 + 4 * d4]);
        a00 += w0.x * s0.x + w0.y * s0.y + w0.z * s0.z + w0.w * s0.w;
        a01 += w0.x * s1.x + w0.y * s1.y + w0.z * s1.z + w0.w * s1.w;
        a10 += w1.x * s0.x + w1.y * s0.y + w1.z * s0.z + w1.w * s0.w;
        a11 += w1.x * s1.x + w1.y * s1.y + w1.z * s1.z + w1.w * s1.w;
    }
    float bA = isQ ? b1[h0 + hg] : 0.f;
    float bB = isQ ? b1[h0 + hg + 16] : 0.f;
    oS[hg * 17 + cg]            = a00 + bA;
    oS[hg * 17 + cg + 8]        = a01 + bA;
    oS[(hg + 16) * 17 + cg]     = a10 + bB;
    oS[(hg + 16) * 17 + cg + 8] = a11 + bB;
    __syncthreads();
#pragma unroll
    for (int r = 0; r < 4; ++r) {
        int i = t + 128 * r;                 // < 512
        int h = i >> 4, c = i & 15;
        dstT[(h0 + h) * stride + row0 + c] = oS[h * 17 + c];
    }
}

// ---------------------------------------------------------------------------
// Fused scores + softmax + PV-partial. Block = 32q x 128k. Grid 32*16 = 512.
// ---------------------------------------------------------------------------
__global__ __launch_bounds__(256) void fused_kernel(
    const float* __restrict__ value, const float* __restrict__ b2,
    float* __restrict__ scores)
{
    __shared__ __align__(16) char smbuf[49152];
    float* const qd = reinterpret_cast<float*>(smbuf);           // [64h][64] dup'd q
    float* const kp = reinterpret_cast<float*>(smbuf + 16384);   // [64h][128k]
    float* const Es = reinterpret_cast<float*>(smbuf);           // phase 2 [32q][128k]
    float* const Vs = reinterpret_cast<float*>(smbuf + 16384);   // phase 2 [64d][128k] swz

    const int t = threadIdx.x;
    const int qt = blockIdx.x >> 4, ks = blockIdx.x & 15;
    const int qb = qt * 32, kb = ks * 128;

    // ---- stage loads ----
#pragma unroll
    for (int r = 0; r < 8; ++r) {
        int i = t + 256 * r;                 // < 2048
        int h = i >> 5, qq = i & 31;
        float v = g_qpT[h * NQ + qb + qq];
        float2 dv = {v, v};
        *reinterpret_cast<float2*>(&qd[h * 64 + 2 * qq]) = dv;
    }
#pragma unroll
    for (int r = 0; r < 8; ++r) {
        int i = t + 256 * r;                 // float4 idx < 2048
        int h = i >> 5, c4 = (i & 31) * 4;
        *reinterpret_cast<float4*>(&kp[h * 128 + c4]) =
            *reinterpret_cast<const float4*>(&g_kpT[h * NK + kb + c4]);
    }
    __syncthreads();

    // ---- phase 1: MLP scores ----
    const int qg = t >> 5, kg = t & 31;      // warp == one qg
    const int q0 = 4 * qg, k0 = 4 * kg;

    ull acc[4][2];
#pragma unroll
    for (int i = 0; i < 4; ++i) { acc[i][0] = 0ULL; acc[i][1] = 0ULL; }

#pragma unroll 4
    for (int h = 0; h < 64; ++h) {
        ull w2 = g_w2d[h];                   // warp-uniform, L1 hit
        ulonglong2 kk_ = *reinterpret_cast<const ulonglong2*>(&kp[h * 128 + k0]);
        // qd pairs for q0..q0+3 are 8 consecutive floats -> 2 broadcast LDS.128
        ulonglong2 qA = *reinterpret_cast<const ulonglong2*>(&qd[h * 64 + 8 * qg]);
        ulonglong2 qB = *reinterpret_cast<const ulonglong2*>(&qd[h * 64 + 8 * qg + 4]);
        acc[0][0] = fmax2(w2, relu2(addx2(qA.x, kk_.x)), acc[0][0]);
        acc[0][1] = fmax2(w2, relu2(addx2(qA.x, kk_.y)), acc[0][1]);
        acc[1][0] = fmax2(w2, relu2(addx2(qA.y, kk_.x)), acc[1][0]);
        acc[1][1] = fmax2(w2, relu2(addx2(qA.y, kk_.y)), acc[1][1]);
        acc[2][0] = fmax2(w2, relu2(addx2(qB.x, kk_.x)), acc[2][0]);
        acc[2][1] = fmax2(w2, relu2(addx2(qB.x, kk_.y)), acc[2][1]);
        acc[3][0] = fmax2(w2, relu2(addx2(qB.y, kk_.x)), acc[3][0]);
        acc[3][1] = fmax2(w2, relu2(addx2(qB.y, kk_.y)), acc[3][1]);
    }

    const float b2v = b2[0];
    float s[4][4];
#pragma unroll
    for (int i = 0; i < 4; ++i) {
        float2 u0 = unpackf2(acc[i][0]);
        float2 u1 = unpackf2(acc[i][1]);
        s[i][0] = u0.x + b2v; s[i][1] = u0.y + b2v;
        s[i][2] = u1.x + b2v; s[i][3] = u1.y + b2v;
        float4 o = {s[i][0], s[i][1], s[i][2], s[i][3]};
        *reinterpret_cast<float4*>(&scores[(qb + q0 + i) * NK + kb + k0]) = o;
    }

    // row max (full-warp reductions; q0 uniform within warp)
    float mx[4];
#pragma unroll
    for (int i = 0; i < 4; ++i) {
        mx[i] = fmaxf(fmaxf(s[i][0], s[i][1]), fmaxf(s[i][2], s[i][3]));
#pragma unroll
        for (int off = 16; off; off >>= 1)
            mx[i] = fmaxf(mx[i], __shfl_xor_sync(0xffffffffu, mx[i], off));
    }
    // exp + row sum
    float e[4][4], sums[4];
#pragma unroll
    for (int i = 0; i < 4; ++i) {
        e[i][0] = __expf(s[i][0] - mx[i]); e[i][1] = __expf(s[i][1] - mx[i]);
        e[i][2] = __expf(s[i][2] - mx[i]); e[i][3] = __expf(s[i][3] - mx[i]);
        sums[i] = (e[i][0] + e[i][1]) + (e[i][2] + e[i][3]);
#pragma unroll
        for (int off = 16; off; off >>= 1)
            sums[i] += __shfl_xor_sync(0xffffffffu, sums[i], off);
    }
    if (kg == 0) {
#pragma unroll
        for (int i = 0; i < 4; ++i) {
            g_ml[ks * NQ + qb + q0 + i] = mx[i];
            g_sl[ks * NQ + qb + q0 + i] = sums[i];
        }
    }
    __syncthreads();                         // phase-1 smem now dead

    // ---- phase 2 staging: Es (exp'd) + Vs (swizzled) ----
#pragma unroll
    for (int i = 0; i < 4; ++i) {
        float4 o = {e[i][0], e[i][1], e[i][2], e[i][3]};
        *reinterpret_cast<float4*>(&Es[(q0 + i) * 128 + k0]) = o;
    }
#pragma unroll
    for (int r = 0; r < 8; ++r) {
        int i = t + 256 * r;                 // float4 idx < 2048
        int d = i >> 5, c4 = (i & 31) * 4;
        float4 v = *reinterpret_cast<const float4*>(&value[d * NK + kb + c4]);
        *reinterpret_cast<float4*>(&Vs[d * 128 + (c4 ^ ((d & 7) << 2))]) = v;
    }
    __syncthreads();

    // ---- GEMM: 128 threads, 8q x 2d per thread, packed over k ----
    ull a2[8][2];
    int dg = t & 31, q0b = 8 * (t >> 5);
    if (t < 128) {
        const int xsw = (dg & 7) << 2;
        const float* VA = &Vs[dg * 128];
        const float* VB = &Vs[(dg + 32) * 128];
#pragma unroll
        for (int i = 0; i < 8; ++i) { a2[i][0] = 0ULL; a2[i][1] = 0ULL; }
#pragma unroll 4
        for (int kk = 0; kk < 32; ++kk) {
            const int kw = 4 * kk;
            const int kwx = kw ^ xsw;
            ulonglong2 v0 = *reinterpret_cast<const ulonglong2*>(&VA[kwx]);
            ulonglong2 v1 = *reinterpret_cast<const ulonglong2*>(&VB[kwx]);
#pragma unroll
            for (int i = 0; i < 8; ++i) {
                ulonglong2 ee = *reinterpret_cast<const ulonglong2*>(&Es[(q0b + i) * 128 + kw]);
                a2[i][0] = fmax2(ee.x, v0.x, a2[i][0]);
                a2[i][0] = fmax2(ee.y, v0.y, a2[i][0]);
                a2[i][1] = fmax2(ee.x, v1.x, a2[i][1]);
                a2[i][1] = fmax2(ee.y, v1.y, a2[i][1]);
            }
        }
    }
    __syncthreads();

    // ---- epilogue: transpose via smem (reuse Es region as [64][33]) ----
    float* EsT = Es;
    if (t < 128) {
#pragma unroll
        for (int i = 0; i < 8; ++i)
#pragma unroll
            for (int j = 0; j < 2; ++j) {
                float2 u = unpackf2(a2[i][j]);
                EsT[(dg + 32 * j) * 33 + q0b + i] = u.x + u.y;
            }
    }
    __syncthreads();
#pragma unroll
    for (int r = 0; r < 8; ++r) {
        int i = t + 256 * r;                 // < 2048
        int d = i >> 5, qq = i & 31;
        g_part[ks * (DD * NQ) + d * NQ + qb + qq] = EsT[d * 33 + qq];
    }
}

// ---------------------------------------------------------------------------
// Reduce (+factor): block = 32 q-cols x 8 d-rows. Grid 32*8 = 256.
// F table in smem, then fully coalesced part streaming.
// ---------------------------------------------------------------------------
__global__ __launch_bounds__(256) void reduce_kernel(float* __restrict__ out)
{
    __shared__ float Fs[16 * 33];            // [s][32q] padded

    const int t = threadIdx.x;
    const int qb = (blockIdx.x & 31) * 32;
    const int d0 = (blockIdx.x >> 5) * 8;

    // factors for 32 q columns; 16 s-lanes per q in 16-lane shfl groups
#pragma unroll
    for (int r = 0; r < 2; ++r) {
        const int s = t & 15, qq = (t >> 4) + 16 * r;
        float ml = g_ml[s * NQ + qb + qq];
        float M = ml;
        M = fmaxf(M, __shfl_xor_sync(0xffffffffu, M, 8, 16));
        M = fmaxf(M, __shfl_xor_sync(0xffffffffu, M, 4, 16));
        M = fmaxf(M, __shfl_xor_sync(0xffffffffu, M, 2, 16));
        M = fmaxf(M, __shfl_xor_sync(0xffffffffu, M, 1, 16));
        float f = __expf(ml - M);
        float p = g_sl[s * NQ + qb + qq] * f;
        p += __shfl_xor_sync(0xffffffffu, p, 8, 16);
        p += __shfl_xor_sync(0xffffffffu, p, 4, 16);
        p += __shfl_xor_sync(0xffffffffu, p, 2, 16);
        p += __shfl_xor_sync(0xffffffffu, p, 1, 16);
        Fs[s * 33 + qq] = f / p;
    }
    __syncthreads();

    // stream partials: 1 output/thread, 16 coalesced 128B loads
    const int q = t & 31, dd = t >> 5;
    float o = 0.f;
#pragma unroll
    for (int ss = 0; ss < KSPLIT; ++ss)
        o = fmaf(g_part[ss * (DD * NQ) + (d0 + dd) * NQ + qb + q], Fs[ss * 33 + q], o);
    out[(d0 + dd) * NQ + qb + q] = o;
}

// ---------------------------------------------------------------------------
extern "C" void kernel_launch(void* const* d_in, const int* in_sizes, int n_in,
                              void* d_out, int out_size)
{
    const float* query = (const float*)d_in[0];   // [1,64,1024]
    const float* key   = (const float*)d_in[1];   // [1,64,2048]
    const float* value = (const float*)d_in[2];   // [1,64,2048]
    const float* W1    = (const float*)d_in[3];   // [64,128]
    const float* b1    = (const float*)d_in[4];   // [64]
    const float* W2    = (const float*)d_in[5];   // [1,64]
    const float* b2    = (const float*)d_in[6];   // [1]

    float* out    = (float*)d_out;                // [1,64,1024]
    float* scores = out + DD * NQ;                // [1,1024,2048]

    proj_kernel<<<(NQ / 16 + NK / 16) * 2, 128>>>(query, key, W1, b1, W2);
    fused_kernel<<<(NQ / 32) * (NK / 128), 256>>>(value, b2, scores);
    reduce_kernel<<<(NQ / 32) * (DD / 8), 256>>>(out);
}